// round 8
// baseline (speedup 1.0000x reference)
#include <cuda_runtime.h>
#include <cuda_bf16.h>
#include <cstdint>

#define NWIN   2048
#define WIN    64
#define DIM    256
#define HEADS  8
#define HD     32
#define QKV_N  768
#define MROWS  (NWIN*WIN)  // 131072

__device__ float g_q[(size_t)NWIN*HEADS*WIN*HD];
__device__ float g_k[(size_t)NWIN*HEADS*WIN*HD];
__device__ float g_v[(size_t)NWIN*HEADS*WIN*HD];
__device__ float g_ao[(size_t)NWIN*WIN*DIM];
__device__ float g_bm[(size_t)256*HEADS*WIN*WIN];  // bias+mask tables (33.5MB)

__device__ __forceinline__ unsigned f2tf32(float f) {
    unsigned r;
    asm("cvt.rna.tf32.f32 %0, %1;" : "=r"(r) : "f"(f));
    return r;
}

__device__ __forceinline__ void mma_tf32(float c[4],
                                         unsigned a0, unsigned a1, unsigned a2, unsigned a3,
                                         unsigned b0, unsigned b1) {
    asm volatile(
        "mma.sync.aligned.m16n8k8.row.col.f32.tf32.tf32.f32 "
        "{%0,%1,%2,%3}, {%4,%5,%6,%7}, {%8,%9}, {%0,%1,%2,%3};"
        : "+f"(c[0]), "+f"(c[1]), "+f"(c[2]), "+f"(c[3])
        : "r"(a0), "r"(a1), "r"(a2), "r"(a3), "r"(b0), "r"(b1));
}

__device__ __forceinline__ void mma_bf16(float c[4],
                                         unsigned a0, unsigned a1, unsigned a2, unsigned a3,
                                         unsigned b0, unsigned b1) {
    asm volatile(
        "mma.sync.aligned.m16n8k16.row.col.f32.bf16.bf16.f32 "
        "{%0,%1,%2,%3}, {%4,%5,%6,%7}, {%8,%9}, {%0,%1,%2,%3};"
        : "+f"(c[0]), "+f"(c[1]), "+f"(c[2]), "+f"(c[3])
        : "r"(a0), "r"(a1), "r"(a2), "r"(a3), "r"(b0), "r"(b1));
}

__device__ __forceinline__ uint32_t pack_bf16(float a, float b) {
    __nv_bfloat162 t = __floats2bfloat162_rn(a, b);
    return *(uint32_t*)&t;
}
__device__ __forceinline__ float bf16hi(float x) {
    return __bfloat162float(__float2bfloat16_rn(x));
}

// ---------------------------------------------------------------------------
// GEMM: C = A @ W^T + bias, K=256. Block 128x128 tile, 256 threads = 8 warps
// (2 warpM x 4 warpN), warp tile 64x32, BK=32, single buffer.
// launch_bounds(256,2) -> <=128 regs -> 2 blocks/SM -> 16 warps/SM.
// ---------------------------------------------------------------------------
#define SA 36

template<bool QKV>
__global__ void __launch_bounds__(256, 2) mma_gemm(const float* __restrict__ A,
                                                   const float* __restrict__ W,
                                                   const float* __restrict__ bias,
                                                   float* __restrict__ out)
{
    const int K = DIM;
    __shared__ unsigned As[128 * SA];
    __shared__ unsigned Bs[128 * SA];

    const int rowBase = blockIdx.y * 128;
    const int colBase = blockIdx.x * 128;
    const int tid  = threadIdx.x;
    const int lane = tid & 31;
    const int warp = tid >> 5;         // 0..7
    const int warpM = warp >> 2;       // 0..1
    const int warpN = warp & 3;        // 0..3
    const int g  = lane >> 2;
    const int tg = lane & 3;
    const int m0 = warpM * 64;
    const int n0 = warpN * 32;

    float acc[4][4][4] = {};           // [m-atom 16][n-atom 8][c]

    for (int kb = 0; kb < K; kb += 32) {
        #pragma unroll
        for (int i = 0; i < 4; i++) {
            const int idx = tid + 256 * i;     // 0..1023
            const int r = idx >> 3, c4 = idx & 7;
            float4 v = *(const float4*)&A[(size_t)(rowBase + r) * K + kb + c4 * 4];
            uint4 u = make_uint4(f2tf32(v.x), f2tf32(v.y), f2tf32(v.z), f2tf32(v.w));
            *(uint4*)&As[r * SA + c4 * 4] = u;
            float4 w = *(const float4*)&W[(size_t)(colBase + r) * K + kb + c4 * 4];
            uint4 uw = make_uint4(f2tf32(w.x), f2tf32(w.y), f2tf32(w.z), f2tf32(w.w));
            *(uint4*)&Bs[r * SA + c4 * 4] = uw;
        }
        __syncthreads();

        #pragma unroll
        for (int ks = 0; ks < 4; ks++) {
            const int k0 = ks * 8;
            unsigned a[4][4];
            #pragma unroll
            for (int am = 0; am < 4; am++) {
                const int mr = m0 + am * 16;
                a[am][0] = As[(mr + g)     * SA + k0 + tg];
                a[am][1] = As[(mr + g + 8) * SA + k0 + tg];
                a[am][2] = As[(mr + g)     * SA + k0 + tg + 4];
                a[am][3] = As[(mr + g + 8) * SA + k0 + tg + 4];
            }
            unsigned bf[4][2];
            #pragma unroll
            for (int an = 0; an < 4; an++) {
                const int nr = n0 + an * 8;
                bf[an][0] = Bs[(nr + g) * SA + k0 + tg];
                bf[an][1] = Bs[(nr + g) * SA + k0 + tg + 4];
            }
            #pragma unroll
            for (int am = 0; am < 4; am++)
                #pragma unroll
                for (int an = 0; an < 4; an++)
                    mma_tf32(acc[am][an], a[am][0], a[am][1], a[am][2], a[am][3],
                             bf[an][0], bf[an][1]);
        }
        __syncthreads();
    }

    #pragma unroll
    for (int am = 0; am < 4; am++) {
        #pragma unroll
        for (int an = 0; an < 4; an++) {
            const int col = colBase + n0 + an * 8 + 2 * tg;
            const float bi0 = bias[col], bi1 = bias[col + 1];
            #pragma unroll
            for (int half = 0; half < 2; half++) {
                const int row = rowBase + m0 + am * 16 + g + 8 * half;
                float2 v;
                v.x = acc[am][an][2 * half]     + bi0;
                v.y = acc[am][an][2 * half + 1] + bi1;
                if (QKV) {
                    const int b = row >> 6, n = row & 63;
                    const int which = col >> 8;
                    const int h = (col >> 5) & 7;
                    const int d = col & 31;
                    float* dst = (which == 0) ? g_q : (which == 1) ? g_k : g_v;
                    *(float2*)&dst[((((size_t)b * HEADS + h) * WIN) + n) * HD + d] = v;
                } else {
                    *(float2*)&out[(size_t)row * DIM + col] = v;
                }
            }
        }
    }
}

// ---------------------------------------------------------------------------
// bias+mask tables
// ---------------------------------------------------------------------------
__global__ void bm_pre(const float* __restrict__ bt, const int* __restrict__ rpi,
                       const float* __restrict__ mask)
{
    const int idx = blockIdx.x * 256 + threadIdx.x;
    const int e = idx & 4095;
    const int h = (idx >> 12) & 7;
    const int w = idx >> 15;
    g_bm[idx] = bt[rpi[e] * HEADS + h] + mask[w * 4096 + e];
}

// ---------------------------------------------------------------------------
// Attention, 3-term bf16 MMA (round-7 proven). One block per (window,head).
// ---------------------------------------------------------------------------
#define QP  40   // bf16 pitch for q/k
#define ATP 68   // fp32 pitch for logits
#define PPB 72   // bf16 pitch for P
#define VTP 72   // bf16 pitch for vt
#define ATTN_SMEM_BYTES 48128

__global__ void __launch_bounds__(128) attn_kernel(const float* __restrict__ logit_scale)
{
    extern __shared__ char smb[];
    float* qs  = (float*)(smb);
    float* ksf = (float*)(smb + 9216);
    float* at  = (float*)(smb);                      // alias (after norm phase)
    __nv_bfloat16* qhi = (__nv_bfloat16*)(smb + 18432);
    __nv_bfloat16* qlo = (__nv_bfloat16*)(smb + 23552);
    __nv_bfloat16* khi = (__nv_bfloat16*)(smb + 28672);
    __nv_bfloat16* klo = (__nv_bfloat16*)(smb + 33792);
    __nv_bfloat16* phi = (__nv_bfloat16*)(smb + 18432);  // alias (after QK)
    __nv_bfloat16* plo = (__nv_bfloat16*)(smb + 27648);  // alias (after QK)
    __nv_bfloat16* vth = (__nv_bfloat16*)(smb + 38912);
    __nv_bfloat16* vtl = (__nv_bfloat16*)(smb + 43520);

    const int bh = blockIdx.x;
    const int b  = bh >> 3;
    const int h  = bh & 7;
    const int tid  = threadIdx.x;
    const int lane = tid & 31;
    const int warp = tid >> 5;       // 0..3
    const int g  = lane >> 2, tg = lane & 3;
    const int m0 = warp * 16;
    const int r0 = m0 + g, r1 = r0 + 8;

    // Phase 0: stage q,k fp32; v -> transposed bf16 hi/lo
    const size_t base = (size_t)bh * WIN * HD;
    #pragma unroll
    for (int i = 0; i < 4; i++) {
        const int idx = tid + 128 * i;            // 0..511
        const int n = idx >> 3, c = (idx & 7) * 4;
        *(float4*)&qs[n * 36 + c]  = *(const float4*)&g_q[base + n * HD + c];
        *(float4*)&ksf[n * 36 + c] = *(const float4*)&g_k[base + n * HD + c];
        float4 v = *(const float4*)&g_v[base + n * HD + c];
        float vv[4] = {v.x, v.y, v.z, v.w};
        #pragma unroll
        for (int j = 0; j < 4; j++) {
            const float hf = bf16hi(vv[j]);
            vth[(c + j) * VTP + n] = __float2bfloat16_rn(hf);
            vtl[(c + j) * VTP + n] = __float2bfloat16_rn(vv[j] - hf);
        }
    }
    __syncthreads();

    // Phase 1: row norm (q with logit scale) + bf16 hi/lo split
    {
        const float ls = __expf(fminf(logit_scale[h], 4.6051701859880914f));
        const int row = tid & 63;
        const float* src = (tid < 64) ? &qs[row * 36] : &ksf[row * 36];
        __nv_bfloat16* dhi = (tid < 64) ? &qhi[row * QP] : &khi[row * QP];
        __nv_bfloat16* dlo = (tid < 64) ? &qlo[row * QP] : &klo[row * QP];
        float s = 0.f;
        #pragma unroll
        for (int d = 0; d < HD; d++) s += src[d] * src[d];
        float inv = 1.0f / fmaxf(sqrtf(s), 1e-12f);
        if (tid < 64) inv *= ls;
        #pragma unroll
        for (int d = 0; d < HD; d += 2) {
            const float x0 = src[d] * inv,     x1 = src[d + 1] * inv;
            const float h0 = bf16hi(x0),       h1 = bf16hi(x1);
            *(uint32_t*)&dhi[d] = pack_bf16(h0, h1);
            *(uint32_t*)&dlo[d] = pack_bf16(x0 - h0, x1 - h1);
        }
    }
    __syncthreads();

    // Phase 2: QK^T, 3-term bf16. warp -> rows [m0,m0+16), all 64 cols.
    float acc[8][4] = {};
    #pragma unroll
    for (int kst = 0; kst < 2; kst++) {
        const int kb = kst * 16;
        unsigned ah[4], al[4];
        ah[0] = *(uint32_t*)&qhi[(m0 + g)     * QP + kb + 2 * tg];
        ah[1] = *(uint32_t*)&qhi[(m0 + g + 8) * QP + kb + 2 * tg];
        ah[2] = *(uint32_t*)&qhi[(m0 + g)     * QP + kb + 2 * tg + 8];
        ah[3] = *(uint32_t*)&qhi[(m0 + g + 8) * QP + kb + 2 * tg + 8];
        al[0] = *(uint32_t*)&qlo[(m0 + g)     * QP + kb + 2 * tg];
        al[1] = *(uint32_t*)&qlo[(m0 + g + 8) * QP + kb + 2 * tg];
        al[2] = *(uint32_t*)&qlo[(m0 + g)     * QP + kb + 2 * tg + 8];
        al[3] = *(uint32_t*)&qlo[(m0 + g + 8) * QP + kb + 2 * tg + 8];
        #pragma unroll
        for (int an = 0; an < 8; an++) {
            const int nr = an * 8;
            unsigned bh0 = *(uint32_t*)&khi[(nr + g) * QP + kb + 2 * tg];
            unsigned bh1 = *(uint32_t*)&khi[(nr + g) * QP + kb + 2 * tg + 8];
            unsigned bl0 = *(uint32_t*)&klo[(nr + g) * QP + kb + 2 * tg];
            unsigned bl1 = *(uint32_t*)&klo[(nr + g) * QP + kb + 2 * tg + 8];
            mma_bf16(acc[an], ah[0], ah[1], ah[2], ah[3], bh0, bh1);
            mma_bf16(acc[an], ah[0], ah[1], ah[2], ah[3], bl0, bl1);
            mma_bf16(acc[an], al[0], al[1], al[2], al[3], bh0, bh1);
        }
    }

    // Add bias+mask from L2-resident table
    {
        const float* bm = g_bm + ((size_t)((b & 255) * 8 + h) << 12);
        #pragma unroll
        for (int an = 0; an < 8; an++) {
            const int c = an * 8 + 2 * tg;
            float2 b0 = *(const float2*)&bm[r0 * 64 + c];
            float2 b1 = *(const float2*)&bm[r1 * 64 + c];
            acc[an][0] += b0.x; acc[an][1] += b0.y;
            acc[an][2] += b1.x; acc[an][3] += b1.y;
        }
    }

    // Store logits fp32 (at aliases qs/ks)
    #pragma unroll
    for (int an = 0; an < 8; an++) {
        const int c = an * 8 + 2 * tg;
        *(float2*)&at[r0 * ATP + c] = make_float2(acc[an][0], acc[an][1]);
        *(float2*)&at[r1 * ATP + c] = make_float2(acc[an][2], acc[an][3]);
    }
    __syncthreads();

    // Phase 3: softmax (warp per row), write P hi/lo bf16 packed
    for (int i = warp; i < WIN; i += 4) {
        float2 a = *(const float2*)&at[i * ATP + 2 * lane];
        float m = fmaxf(a.x, a.y);
        #pragma unroll
        for (int o = 16; o; o >>= 1) m = fmaxf(m, __shfl_xor_sync(0xffffffffu, m, o));
        float e0 = __expf(a.x - m), e1 = __expf(a.y - m);
        float s = e0 + e1;
        #pragma unroll
        for (int o = 16; o; o >>= 1) s += __shfl_xor_sync(0xffffffffu, s, o);
        const float rinv = 1.0f / s;
        e0 *= rinv; e1 *= rinv;
        const float h0 = bf16hi(e0), h1 = bf16hi(e1);
        *(uint32_t*)&phi[i * PPB + 2 * lane] = pack_bf16(h0, h1);
        *(uint32_t*)&plo[i * PPB + 2 * lane] = pack_bf16(e0 - h0, e1 - h1);
    }
    __syncthreads();

    // Phase 4: out = P @ V, 3-term bf16.
    float oacc[4][4] = {};
    #pragma unroll
    for (int kst = 0; kst < 4; kst++) {
        const int kb = kst * 16;
        unsigned ah[4], al[4];
        ah[0] = *(uint32_t*)&phi[(m0 + g)     * PPB + kb + 2 * tg];
        ah[1] = *(uint32_t*)&phi[(m0 + g + 8) * PPB + kb + 2 * tg];
        ah[2] = *(uint32_t*)&phi[(m0 + g)     * PPB + kb + 2 * tg + 8];
        ah[3] = *(uint32_t*)&phi[(m0 + g + 8) * PPB + kb + 2 * tg + 8];
        al[0] = *(uint32_t*)&plo[(m0 + g)     * PPB + kb + 2 * tg];
        al[1] = *(uint32_t*)&plo[(m0 + g + 8) * PPB + kb + 2 * tg];
        al[2] = *(uint32_t*)&plo[(m0 + g)     * PPB + kb + 2 * tg + 8];
        al[3] = *(uint32_t*)&plo[(m0 + g + 8) * PPB + kb + 2 * tg + 8];
        #pragma unroll
        for (int dn = 0; dn < 4; dn++) {
            const int nn = dn * 8;
            unsigned bh0 = *(uint32_t*)&vth[(nn + g) * VTP + kb + 2 * tg];
            unsigned bh1 = *(uint32_t*)&vth[(nn + g) * VTP + kb + 2 * tg + 8];
            unsigned bl0 = *(uint32_t*)&vtl[(nn + g) * VTP + kb + 2 * tg];
            unsigned bl1 = *(uint32_t*)&vtl[(nn + g) * VTP + kb + 2 * tg + 8];
            mma_bf16(oacc[dn], ah[0], ah[1], ah[2], ah[3], bh0, bh1);
            mma_bf16(oacc[dn], ah[0], ah[1], ah[2], ah[3], bl0, bl1);
            mma_bf16(oacc[dn], al[0], al[1], al[2], al[3], bh0, bh1);
        }
    }

    float* aop = g_ao + (size_t)b * WIN * DIM + h * HD;
    #pragma unroll
    for (int dn = 0; dn < 4; dn++) {
        const int c = dn * 8 + 2 * tg;
        *(float2*)&aop[(size_t)r0 * DIM + c] = make_float2(oacc[dn][0], oacc[dn][1]);
        *(float2*)&aop[(size_t)r1 * DIM + c] = make_float2(oacc[dn][2], oacc[dn][3]);
    }
}

// ---------------------------------------------------------------------------
extern "C" void kernel_launch(void* const* d_in, const int* in_sizes, int n_in,
                              void* d_out, int out_size)
{
    const float* x        = (const float*)d_in[0];
    const float* mask     = (const float*)d_in[1];
    const float* qkv_w    = (const float*)d_in[2];
    const float* qkv_b    = (const float*)d_in[3];
    const float* proj_w   = (const float*)d_in[4];
    const float* proj_b   = (const float*)d_in[5];
    const float* lscale   = (const float*)d_in[6];
    const float* btable   = (const float*)d_in[7];
    const int*   rpi      = (const int*)d_in[8];
    float* out = (float*)d_out;

    cudaFuncSetAttribute(attn_kernel, cudaFuncAttributeMaxDynamicSharedMemorySize,
                         ATTN_SMEM_BYTES);

    // 0) bias+mask tables
    bm_pre<<<32768, 256>>>(btable, rpi, mask);
    // 1) QKV projection
    {
        dim3 grid(QKV_N / 128, MROWS / 128);
        mma_gemm<true><<<grid, 256>>>(x, qkv_w, qkv_b, nullptr);
    }
    // 2) Attention per (window, head)
    {
        attn_kernel<<<NWIN * HEADS, 128, ATTN_SMEM_BYTES>>>(lscale);
    }
    // 3) Output projection
    {
        float* ao = nullptr;
        cudaGetSymbolAddress((void**)&ao, g_ao);
        dim3 grid(DIM / 128, MROWS / 128);
        mma_gemm<false><<<grid, 256>>>(ao, proj_w, proj_b, out);
    }
}

// round 9
// speedup vs baseline: 1.2706x; 1.2706x over previous
#include <cuda_runtime.h>
#include <cuda_bf16.h>
#include <cstdint>

#define NWIN   2048
#define WIN    64
#define DIM    256
#define HEADS  8
#define HD     32
#define QKV_N  768
#define MROWS  (NWIN*WIN)  // 131072

__device__ float g_q[(size_t)NWIN*HEADS*WIN*HD];
__device__ float g_k[(size_t)NWIN*HEADS*WIN*HD];
__device__ float g_v[(size_t)NWIN*HEADS*WIN*HD];
__device__ float g_ao[(size_t)NWIN*WIN*DIM];
__device__ float g_bm[(size_t)256*HEADS*WIN*WIN];  // bias+mask tables (33.5MB)

__device__ __forceinline__ unsigned f2tf32(float f) {
    unsigned r;
    asm("cvt.rna.tf32.f32 %0, %1;" : "=r"(r) : "f"(f));
    return r;
}

__device__ __forceinline__ void mma_tf32(float c[4],
                                         unsigned a0, unsigned a1, unsigned a2, unsigned a3,
                                         unsigned b0, unsigned b1) {
    asm volatile(
        "mma.sync.aligned.m16n8k8.row.col.f32.tf32.tf32.f32 "
        "{%0,%1,%2,%3}, {%4,%5,%6,%7}, {%8,%9}, {%0,%1,%2,%3};"
        : "+f"(c[0]), "+f"(c[1]), "+f"(c[2]), "+f"(c[3])
        : "r"(a0), "r"(a1), "r"(a2), "r"(a3), "r"(b0), "r"(b1));
}

__device__ __forceinline__ void mma_bf16(float c[4],
                                         unsigned a0, unsigned a1, unsigned a2, unsigned a3,
                                         unsigned b0, unsigned b1) {
    asm volatile(
        "mma.sync.aligned.m16n8k16.row.col.f32.bf16.bf16.f32 "
        "{%0,%1,%2,%3}, {%4,%5,%6,%7}, {%8,%9}, {%0,%1,%2,%3};"
        : "+f"(c[0]), "+f"(c[1]), "+f"(c[2]), "+f"(c[3])
        : "r"(a0), "r"(a1), "r"(a2), "r"(a3), "r"(b0), "r"(b1));
}

__device__ __forceinline__ uint32_t pack_bf16(float a, float b) {
    __nv_bfloat162 t = __floats2bfloat162_rn(a, b);
    return *(uint32_t*)&t;
}
__device__ __forceinline__ float bf16hi(float x) {
    return __bfloat162float(__float2bfloat16_rn(x));
}

// ---------------------------------------------------------------------------
// GEMM (round-7 proven): C = A @ W^T + bias, K=256. Block 128x128, 4 warps,
// warp 64x64, BK=32, single buffer, launch_bounds(128,2).
// ---------------------------------------------------------------------------
#define SA 36

template<bool QKV>
__global__ void __launch_bounds__(128, 2) mma_gemm(const float* __restrict__ A,
                                                   const float* __restrict__ W,
                                                   const float* __restrict__ bias,
                                                   float* __restrict__ out)
{
    const int K = DIM;
    __shared__ unsigned As[128 * SA];
    __shared__ unsigned Bs[128 * SA];

    const int rowBase = blockIdx.y * 128;
    const int colBase = blockIdx.x * 128;
    const int tid  = threadIdx.x;
    const int lane = tid & 31;
    const int warp = tid >> 5;
    const int warpM = warp >> 1;
    const int warpN = warp & 1;
    const int g  = lane >> 2;
    const int tg = lane & 3;
    const int m0 = warpM * 64;
    const int n0 = warpN * 64;

    float acc[4][8][4] = {};

    for (int kb = 0; kb < K; kb += 32) {
        #pragma unroll
        for (int i = 0; i < 8; i++) {
            const int idx = tid + 128 * i;
            const int r = idx >> 3, c4 = idx & 7;
            float4 v = *(const float4*)&A[(size_t)(rowBase + r) * K + kb + c4 * 4];
            uint4 u = make_uint4(f2tf32(v.x), f2tf32(v.y), f2tf32(v.z), f2tf32(v.w));
            *(uint4*)&As[r * SA + c4 * 4] = u;
            float4 w = *(const float4*)&W[(size_t)(colBase + r) * K + kb + c4 * 4];
            uint4 uw = make_uint4(f2tf32(w.x), f2tf32(w.y), f2tf32(w.z), f2tf32(w.w));
            *(uint4*)&Bs[r * SA + c4 * 4] = uw;
        }
        __syncthreads();

        #pragma unroll
        for (int ks = 0; ks < 4; ks++) {
            const int k0 = ks * 8;
            unsigned a[4][4];
            #pragma unroll
            for (int am = 0; am < 4; am++) {
                const int mr = m0 + am * 16;
                a[am][0] = As[(mr + g)     * SA + k0 + tg];
                a[am][1] = As[(mr + g + 8) * SA + k0 + tg];
                a[am][2] = As[(mr + g)     * SA + k0 + tg + 4];
                a[am][3] = As[(mr + g + 8) * SA + k0 + tg + 4];
            }
            unsigned bf[8][2];
            #pragma unroll
            for (int an = 0; an < 8; an++) {
                const int nr = n0 + an * 8;
                bf[an][0] = Bs[(nr + g) * SA + k0 + tg];
                bf[an][1] = Bs[(nr + g) * SA + k0 + tg + 4];
            }
            #pragma unroll
            for (int am = 0; am < 4; am++)
                #pragma unroll
                for (int an = 0; an < 8; an++)
                    mma_tf32(acc[am][an], a[am][0], a[am][1], a[am][2], a[am][3],
                             bf[an][0], bf[an][1]);
        }
        __syncthreads();
    }

    #pragma unroll
    for (int am = 0; am < 4; am++) {
        #pragma unroll
        for (int an = 0; an < 8; an++) {
            const int col = colBase + n0 + an * 8 + 2 * tg;
            const float bi0 = bias[col], bi1 = bias[col + 1];
            #pragma unroll
            for (int half = 0; half < 2; half++) {
                const int row = rowBase + m0 + am * 16 + g + 8 * half;
                float2 v;
                v.x = acc[am][an][2 * half]     + bi0;
                v.y = acc[am][an][2 * half + 1] + bi1;
                if (QKV) {
                    const int b = row >> 6, n = row & 63;
                    const int which = col >> 8;
                    const int h = (col >> 5) & 7;
                    const int d = col & 31;
                    float* dst = (which == 0) ? g_q : (which == 1) ? g_k : g_v;
                    *(float2*)&dst[((((size_t)b * HEADS + h) * WIN) + n) * HD + d] = v;
                } else {
                    *(float2*)&out[(size_t)row * DIM + col] = v;
                }
            }
        }
    }
}

// ---------------------------------------------------------------------------
// bias+mask tables
// ---------------------------------------------------------------------------
__global__ void bm_pre(const float* __restrict__ bt, const int* __restrict__ rpi,
                       const float* __restrict__ mask)
{
    const int idx = blockIdx.x * 256 + threadIdx.x;
    const int e = idx & 4095;
    const int h = (idx >> 12) & 7;
    const int w = idx >> 15;
    g_bm[idx] = bt[rpi[e] * HEADS + h] + mask[w * 4096 + e];
}

// ---------------------------------------------------------------------------
// Attention v3: latency-lean. One block per (window,head), 128 threads.
// - q/k loaded straight to registers (half-row per thread), norm via shfl,
//   bf16 hi/lo written directly to smem (no fp32 staging).
// - bias+mask prefetched to registers BEFORE the QK MMA phase.
// - register softmax (shfl over tg), P hi/lo aliases q/k smem.
// smem: qhi@0 qlo@5120 khi@10240 klo@15360 vth@20480 vtl@25088 (29696 B);
//       phi aliases @0, plo @10240 (after QK reads complete).
// ---------------------------------------------------------------------------
#define QP  40   // bf16 pitch q/k
#define PPB 72   // bf16 pitch P
#define VTP 72   // bf16 pitch vt
#define ATTN_SMEM_BYTES 29696

__global__ void __launch_bounds__(128) attn_kernel(const float* __restrict__ logit_scale)
{
    extern __shared__ char smb[];
    __nv_bfloat16* qhi = (__nv_bfloat16*)(smb);
    __nv_bfloat16* qlo = (__nv_bfloat16*)(smb + 5120);
    __nv_bfloat16* khi = (__nv_bfloat16*)(smb + 10240);
    __nv_bfloat16* klo = (__nv_bfloat16*)(smb + 15360);
    __nv_bfloat16* vth = (__nv_bfloat16*)(smb + 20480);
    __nv_bfloat16* vtl = (__nv_bfloat16*)(smb + 25088);
    __nv_bfloat16* phi = (__nv_bfloat16*)(smb);           // alias (after QK)
    __nv_bfloat16* plo = (__nv_bfloat16*)(smb + 10240);   // alias (after QK)

    const int bh = blockIdx.x;
    const int b  = bh >> 3;
    const int h  = bh & 7;
    const int tid  = threadIdx.x;
    const int lane = tid & 31;
    const int warp = tid >> 5;       // 0..3
    const int g  = lane >> 2, tg = lane & 3;
    const int m0 = warp * 16;
    const int r0 = m0 + g, r1 = r0 + 8;

    const size_t base = (size_t)bh * WIN * HD;
    const float ls = __expf(fminf(logit_scale[h], 4.6051701859880914f));

    // Phase 0: q and k — half-row per thread, registers only
    {
        const int row = tid >> 1;
        const int d0  = (tid & 1) * 16;
        // q
        float qv[16];
        #pragma unroll
        for (int i = 0; i < 4; i++)
            *(float4*)&qv[4 * i] = *(const float4*)&g_q[base + row * HD + d0 + 4 * i];
        float s = 0.f;
        #pragma unroll
        for (int i = 0; i < 16; i++) s += qv[i] * qv[i];
        s += __shfl_xor_sync(0xffffffffu, s, 1);
        float inv = ls / fmaxf(sqrtf(s), 1e-12f);
        #pragma unroll
        for (int i = 0; i < 16; i += 2) {
            const float x0 = qv[i] * inv, x1 = qv[i + 1] * inv;
            const float h0 = bf16hi(x0), h1 = bf16hi(x1);
            *(uint32_t*)&qhi[row * QP + d0 + i] = pack_bf16(h0, h1);
            *(uint32_t*)&qlo[row * QP + d0 + i] = pack_bf16(x0 - h0, x1 - h1);
        }
        // k
        float kv[16];
        #pragma unroll
        for (int i = 0; i < 4; i++)
            *(float4*)&kv[4 * i] = *(const float4*)&g_k[base + row * HD + d0 + 4 * i];
        s = 0.f;
        #pragma unroll
        for (int i = 0; i < 16; i++) s += kv[i] * kv[i];
        s += __shfl_xor_sync(0xffffffffu, s, 1);
        inv = 1.0f / fmaxf(sqrtf(s), 1e-12f);
        #pragma unroll
        for (int i = 0; i < 16; i += 2) {
            const float x0 = kv[i] * inv, x1 = kv[i + 1] * inv;
            const float h0 = bf16hi(x0), h1 = bf16hi(x1);
            *(uint32_t*)&khi[row * QP + d0 + i] = pack_bf16(h0, h1);
            *(uint32_t*)&klo[row * QP + d0 + i] = pack_bf16(x0 - h0, x1 - h1);
        }
        // v -> transposed bf16 hi/lo
        #pragma unroll
        for (int i = 0; i < 4; i++) {
            const int idx = tid + 128 * i;            // 0..511
            const int n = idx >> 3, c = (idx & 7) * 4;
            float4 v = *(const float4*)&g_v[base + n * HD + c];
            float vv[4] = {v.x, v.y, v.z, v.w};
            #pragma unroll
            for (int j = 0; j < 4; j++) {
                const float hf = bf16hi(vv[j]);
                vth[(c + j) * VTP + n] = __float2bfloat16_rn(hf);
                vtl[(c + j) * VTP + n] = __float2bfloat16_rn(vv[j] - hf);
            }
        }
    }
    __syncthreads();

    // Prefetch bias+mask for this thread's fragment (hides L2 behind MMAs)
    float2 bm0[8], bm1[8];
    {
        const float* bm = g_bm + ((size_t)((b & 255) * 8 + h) << 12);
        #pragma unroll
        for (int an = 0; an < 8; an++) {
            const int c = an * 8 + 2 * tg;
            bm0[an] = *(const float2*)&bm[r0 * 64 + c];
            bm1[an] = *(const float2*)&bm[r1 * 64 + c];
        }
    }

    // Phase 1: QK^T, 3-term bf16. warp -> rows [m0,m0+16), all 64 cols.
    float acc[8][4] = {};
    #pragma unroll
    for (int kst = 0; kst < 2; kst++) {
        const int kb = kst * 16;
        unsigned ah[4], al[4];
        ah[0] = *(uint32_t*)&qhi[(m0 + g)     * QP + kb + 2 * tg];
        ah[1] = *(uint32_t*)&qhi[(m0 + g + 8) * QP + kb + 2 * tg];
        ah[2] = *(uint32_t*)&qhi[(m0 + g)     * QP + kb + 2 * tg + 8];
        ah[3] = *(uint32_t*)&qhi[(m0 + g + 8) * QP + kb + 2 * tg + 8];
        al[0] = *(uint32_t*)&qlo[(m0 + g)     * QP + kb + 2 * tg];
        al[1] = *(uint32_t*)&qlo[(m0 + g + 8) * QP + kb + 2 * tg];
        al[2] = *(uint32_t*)&qlo[(m0 + g)     * QP + kb + 2 * tg + 8];
        al[3] = *(uint32_t*)&qlo[(m0 + g + 8) * QP + kb + 2 * tg + 8];
        #pragma unroll
        for (int an = 0; an < 8; an++) {
            const int nr = an * 8;
            unsigned bh0 = *(uint32_t*)&khi[(nr + g) * QP + kb + 2 * tg];
            unsigned bh1 = *(uint32_t*)&khi[(nr + g) * QP + kb + 2 * tg + 8];
            unsigned bl0 = *(uint32_t*)&klo[(nr + g) * QP + kb + 2 * tg];
            unsigned bl1 = *(uint32_t*)&klo[(nr + g) * QP + kb + 2 * tg + 8];
            mma_bf16(acc[an], ah[0], ah[1], ah[2], ah[3], bh0, bh1);
            mma_bf16(acc[an], ah[0], ah[1], ah[2], ah[3], bl0, bl1);
            mma_bf16(acc[an], al[0], al[1], al[2], al[3], bh0, bh1);
        }
    }
    __syncthreads();   // all QK smem reads done before P writes alias q/k

    // Phase 2: bias+mask add + register softmax (rows r0, r1)
    {
        float m0v = -1e30f, m1v = -1e30f;
        #pragma unroll
        for (int an = 0; an < 8; an++) {
            acc[an][0] += bm0[an].x; acc[an][1] += bm0[an].y;
            acc[an][2] += bm1[an].x; acc[an][3] += bm1[an].y;
            m0v = fmaxf(m0v, fmaxf(acc[an][0], acc[an][1]));
            m1v = fmaxf(m1v, fmaxf(acc[an][2], acc[an][3]));
        }
        m0v = fmaxf(m0v, __shfl_xor_sync(0xffffffffu, m0v, 1));
        m0v = fmaxf(m0v, __shfl_xor_sync(0xffffffffu, m0v, 2));
        m1v = fmaxf(m1v, __shfl_xor_sync(0xffffffffu, m1v, 1));
        m1v = fmaxf(m1v, __shfl_xor_sync(0xffffffffu, m1v, 2));
        float s0 = 0.f, s1 = 0.f;
        #pragma unroll
        for (int an = 0; an < 8; an++) {
            acc[an][0] = __expf(acc[an][0] - m0v); s0 += acc[an][0];
            acc[an][1] = __expf(acc[an][1] - m0v); s0 += acc[an][1];
            acc[an][2] = __expf(acc[an][2] - m1v); s1 += acc[an][2];
            acc[an][3] = __expf(acc[an][3] - m1v); s1 += acc[an][3];
        }
        s0 += __shfl_xor_sync(0xffffffffu, s0, 1);
        s0 += __shfl_xor_sync(0xffffffffu, s0, 2);
        s1 += __shfl_xor_sync(0xffffffffu, s1, 1);
        s1 += __shfl_xor_sync(0xffffffffu, s1, 2);
        const float i0 = 1.0f / s0, i1 = 1.0f / s1;
        #pragma unroll
        for (int an = 0; an < 8; an++) {
            const int c = an * 8 + 2 * tg;
            const float p00 = acc[an][0] * i0, p01 = acc[an][1] * i0;
            const float p10 = acc[an][2] * i1, p11 = acc[an][3] * i1;
            const float h00 = bf16hi(p00), h01 = bf16hi(p01);
            const float h10 = bf16hi(p10), h11 = bf16hi(p11);
            *(uint32_t*)&phi[r0 * PPB + c] = pack_bf16(h00, h01);
            *(uint32_t*)&phi[r1 * PPB + c] = pack_bf16(h10, h11);
            *(uint32_t*)&plo[r0 * PPB + c] = pack_bf16(p00 - h00, p01 - h01);
            *(uint32_t*)&plo[r1 * PPB + c] = pack_bf16(p10 - h10, p11 - h11);
        }
    }
    __syncwarp();   // warp reads only its own 16 P-rows

    // Phase 3: out = P @ V, 3-term bf16.
    float oacc[4][4] = {};
    #pragma unroll
    for (int kst = 0; kst < 4; kst++) {
        const int kb = kst * 16;
        unsigned ah[4], al[4];
        ah[0] = *(uint32_t*)&phi[(m0 + g)     * PPB + kb + 2 * tg];
        ah[1] = *(uint32_t*)&phi[(m0 + g + 8) * PPB + kb + 2 * tg];
        ah[2] = *(uint32_t*)&phi[(m0 + g)     * PPB + kb + 2 * tg + 8];
        ah[3] = *(uint32_t*)&phi[(m0 + g + 8) * PPB + kb + 2 * tg + 8];
        al[0] = *(uint32_t*)&plo[(m0 + g)     * PPB + kb + 2 * tg];
        al[1] = *(uint32_t*)&plo[(m0 + g + 8) * PPB + kb + 2 * tg];
        al[2] = *(uint32_t*)&plo[(m0 + g)     * PPB + kb + 2 * tg + 8];
        al[3] = *(uint32_t*)&plo[(m0 + g + 8) * PPB + kb + 2 * tg + 8];
        #pragma unroll
        for (int dn = 0; dn < 4; dn++) {
            const int nn = dn * 8;
            unsigned bh0 = *(uint32_t*)&vth[(nn + g) * VTP + kb + 2 * tg];
            unsigned bh1 = *(uint32_t*)&vth[(nn + g) * VTP + kb + 2 * tg + 8];
            unsigned bl0 = *(uint32_t*)&vtl[(nn + g) * VTP + kb + 2 * tg];
            unsigned bl1 = *(uint32_t*)&vtl[(nn + g) * VTP + kb + 2 * tg + 8];
            mma_bf16(oacc[dn], ah[0], ah[1], ah[2], ah[3], bh0, bh1);
            mma_bf16(oacc[dn], ah[0], ah[1], ah[2], ah[3], bl0, bl1);
            mma_bf16(oacc[dn], al[0], al[1], al[2], al[3], bh0, bh1);
        }
    }

    float* aop = g_ao + (size_t)b * WIN * DIM + h * HD;
    #pragma unroll
    for (int dn = 0; dn < 4; dn++) {
        const int c = dn * 8 + 2 * tg;
        *(float2*)&aop[(size_t)r0 * DIM + c] = make_float2(oacc[dn][0], oacc[dn][1]);
        *(float2*)&aop[(size_t)r1 * DIM + c] = make_float2(oacc[dn][2], oacc[dn][3]);
    }
}

// ---------------------------------------------------------------------------
extern "C" void kernel_launch(void* const* d_in, const int* in_sizes, int n_in,
                              void* d_out, int out_size)
{
    const float* x        = (const float*)d_in[0];
    const float* mask     = (const float*)d_in[1];
    const float* qkv_w    = (const float*)d_in[2];
    const float* qkv_b    = (const float*)d_in[3];
    const float* proj_w   = (const float*)d_in[4];
    const float* proj_b   = (const float*)d_in[5];
    const float* lscale   = (const float*)d_in[6];
    const float* btable   = (const float*)d_in[7];
    const int*   rpi      = (const int*)d_in[8];
    float* out = (float*)d_out;

    cudaFuncSetAttribute(attn_kernel, cudaFuncAttributeMaxDynamicSharedMemorySize,
                         ATTN_SMEM_BYTES);

    // 0) bias+mask tables
    bm_pre<<<32768, 256>>>(btable, rpi, mask);
    // 1) QKV projection
    {
        dim3 grid(QKV_N / 128, MROWS / 128);
        mma_gemm<true><<<grid, 128>>>(x, qkv_w, qkv_b, nullptr);
    }
    // 2) Attention per (window, head)
    {
        attn_kernel<<<NWIN * HEADS, 128, ATTN_SMEM_BYTES>>>(lscale);
    }
    // 3) Output projection
    {
        float* ao = nullptr;
        cudaGetSymbolAddress((void**)&ao, g_ao);
        dim3 grid(DIM / 128, MROWS / 128);
        mma_gemm<false><<<grid, 128>>>(ao, proj_w, proj_b, out);
    }
}

// round 11
// speedup vs baseline: 1.4204x; 1.1179x over previous
#include <cuda_runtime.h>
#include <cuda_bf16.h>
#include <cuda_fp16.h>
#include <cstdint>

#define NWIN   2048
#define WIN    64
#define DIM    256
#define HEADS  8
#define HD     32
#define QKV_N  768
#define MROWS  (NWIN*WIN)  // 131072

__device__ float g_q[(size_t)NWIN*HEADS*WIN*HD];
__device__ float g_k[(size_t)NWIN*HEADS*WIN*HD];
__device__ float g_v[(size_t)NWIN*HEADS*WIN*HD];
__device__ float g_ao[(size_t)NWIN*WIN*DIM];
__device__ float g_bm[(size_t)256*HEADS*WIN*WIN];  // bias+mask tables (33.5MB)

__device__ __forceinline__ uint32_t pack_bf16(float a, float b) {
    __nv_bfloat162 t = __floats2bfloat162_rn(a, b);
    return *(uint32_t*)&t;
}
__device__ __forceinline__ float bf16hi(float x) {
    return __bfloat162float(__float2bfloat16_rn(x));
}
__device__ __forceinline__ uint32_t pack_f16(float a, float b) {
    __half2 t = __floats2half2_rn(a, b);
    return *(uint32_t*)&t;
}

__device__ __forceinline__ void mma_bf16(float c[4],
                                         unsigned a0, unsigned a1, unsigned a2, unsigned a3,
                                         unsigned b0, unsigned b1) {
    asm volatile(
        "mma.sync.aligned.m16n8k16.row.col.f32.bf16.bf16.f32 "
        "{%0,%1,%2,%3}, {%4,%5,%6,%7}, {%8,%9}, {%0,%1,%2,%3};"
        : "+f"(c[0]), "+f"(c[1]), "+f"(c[2]), "+f"(c[3])
        : "r"(a0), "r"(a1), "r"(a2), "r"(a3), "r"(b0), "r"(b1));
}

__device__ __forceinline__ void mma_f16(float c[4],
                                        unsigned a0, unsigned a1, unsigned a2, unsigned a3,
                                        unsigned b0, unsigned b1) {
    asm volatile(
        "mma.sync.aligned.m16n8k16.row.col.f32.f16.f16.f32 "
        "{%0,%1,%2,%3}, {%4,%5,%6,%7}, {%8,%9}, {%0,%1,%2,%3};"
        : "+f"(c[0]), "+f"(c[1]), "+f"(c[2]), "+f"(c[3])
        : "r"(a0), "r"(a1), "r"(a2), "r"(a3), "r"(b0), "r"(b1));
}

// ---------------------------------------------------------------------------
// GEMM: C = A @ W^T + bias, K=256, fp16 single-pass (fp32 accumulate).
// Block 128x128, 4 warps, warp 64x64, BK=32, single buffer.
// fp16 m16n8k16: half the MMA instructions & half the fragment LDS of tf32 k8.
// smem pitch 40 halves -> fragment LDS bank = (20*row + tg) mod 32: conflict-free.
// ---------------------------------------------------------------------------
#define GP 40   // smem pitch in halves

template<bool QKV>
__global__ void __launch_bounds__(128, 2) mma_gemm(const float* __restrict__ A,
                                                   const float* __restrict__ W,
                                                   const float* __restrict__ bias,
                                                   float* __restrict__ out)
{
    const int K = DIM;
    __shared__ __half As[128 * GP];
    __shared__ __half Bs[128 * GP];

    const int rowBase = blockIdx.y * 128;
    const int colBase = blockIdx.x * 128;
    const int tid  = threadIdx.x;
    const int lane = tid & 31;
    const int warp = tid >> 5;
    const int warpM = warp >> 1;
    const int warpN = warp & 1;
    const int g  = lane >> 2;
    const int tg = lane & 3;
    const int m0 = warpM * 64;
    const int n0 = warpN * 64;

    float acc[4][8][4] = {};

    for (int kb = 0; kb < K; kb += 32) {
        // load A,B tiles (128x32 fp32 -> fp16), 8-half chunks: 512 per tile
        #pragma unroll
        for (int i = 0; i < 4; i++) {
            const int idx = tid + 128 * i;        // 0..511
            const int r = idx >> 2, c8 = (idx & 3) * 8;
            float4 v0 = *(const float4*)&A[(size_t)(rowBase + r) * K + kb + c8];
            float4 v1 = *(const float4*)&A[(size_t)(rowBase + r) * K + kb + c8 + 4];
            uint4 u = make_uint4(pack_f16(v0.x, v0.y), pack_f16(v0.z, v0.w),
                                 pack_f16(v1.x, v1.y), pack_f16(v1.z, v1.w));
            *(uint4*)&As[r * GP + c8] = u;
            float4 w0 = *(const float4*)&W[(size_t)(colBase + r) * K + kb + c8];
            float4 w1 = *(const float4*)&W[(size_t)(colBase + r) * K + kb + c8 + 4];
            uint4 uw = make_uint4(pack_f16(w0.x, w0.y), pack_f16(w0.z, w0.w),
                                  pack_f16(w1.x, w1.y), pack_f16(w1.z, w1.w));
            *(uint4*)&Bs[r * GP + c8] = uw;
        }
        __syncthreads();

        #pragma unroll
        for (int ks = 0; ks < 2; ks++) {
            const int k0 = ks * 16;
            unsigned a[4][4];
            #pragma unroll
            for (int am = 0; am < 4; am++) {
                const int mr = m0 + am * 16;
                a[am][0] = *(const uint32_t*)&As[(mr + g)     * GP + k0 + 2 * tg];
                a[am][1] = *(const uint32_t*)&As[(mr + g + 8) * GP + k0 + 2 * tg];
                a[am][2] = *(const uint32_t*)&As[(mr + g)     * GP + k0 + 2 * tg + 8];
                a[am][3] = *(const uint32_t*)&As[(mr + g + 8) * GP + k0 + 2 * tg + 8];
            }
            unsigned bf[8][2];
            #pragma unroll
            for (int an = 0; an < 8; an++) {
                const int nr = n0 + an * 8;
                bf[an][0] = *(const uint32_t*)&Bs[(nr + g) * GP + k0 + 2 * tg];
                bf[an][1] = *(const uint32_t*)&Bs[(nr + g) * GP + k0 + 2 * tg + 8];
            }
            #pragma unroll
            for (int am = 0; am < 4; am++)
                #pragma unroll
                for (int an = 0; an < 8; an++)
                    mma_f16(acc[am][an], a[am][0], a[am][1], a[am][2], a[am][3],
                            bf[an][0], bf[an][1]);
        }
        __syncthreads();
    }

    #pragma unroll
    for (int am = 0; am < 4; am++) {
        #pragma unroll
        for (int an = 0; an < 8; an++) {
            const int col = colBase + n0 + an * 8 + 2 * tg;
            const float bi0 = bias[col], bi1 = bias[col + 1];
            #pragma unroll
            for (int half = 0; half < 2; half++) {
                const int row = rowBase + m0 + am * 16 + g + 8 * half;
                float2 v;
                v.x = acc[am][an][2 * half]     + bi0;
                v.y = acc[am][an][2 * half + 1] + bi1;
                if (QKV) {
                    const int b = row >> 6, n = row & 63;
                    const int which = col >> 8;
                    const int h = (col >> 5) & 7;
                    const int d = col & 31;
                    float* dst = (which == 0) ? g_q : (which == 1) ? g_k : g_v;
                    *(float2*)&dst[((((size_t)b * HEADS + h) * WIN) + n) * HD + d] = v;
                } else {
                    *(float2*)&out[(size_t)row * DIM + col] = v;
                }
            }
        }
    }
}

// ---------------------------------------------------------------------------
// bias+mask tables
// ---------------------------------------------------------------------------
__global__ void bm_pre(const float* __restrict__ bt, const int* __restrict__ rpi,
                       const float* __restrict__ mask)
{
    const int idx = blockIdx.x * 256 + threadIdx.x;
    const int e = idx & 4095;
    const int h = (idx >> 12) & 7;
    const int w = idx >> 15;
    g_bm[idx] = bt[rpi[e] * HEADS + h] + mask[w * 4096 + e];
}

// ---------------------------------------------------------------------------
// Attention (round-9 proven): latency-lean, 3-term bf16, 128 threads.
// ---------------------------------------------------------------------------
#define QP  40
#define PPB 72
#define VTP 72
#define ATTN_SMEM_BYTES 29696

__global__ void __launch_bounds__(128) attn_kernel(const float* __restrict__ logit_scale)
{
    extern __shared__ char smb[];
    __nv_bfloat16* qhi = (__nv_bfloat16*)(smb);
    __nv_bfloat16* qlo = (__nv_bfloat16*)(smb + 5120);
    __nv_bfloat16* khi = (__nv_bfloat16*)(smb + 10240);
    __nv_bfloat16* klo = (__nv_bfloat16*)(smb + 15360);
    __nv_bfloat16* vth = (__nv_bfloat16*)(smb + 20480);
    __nv_bfloat16* vtl = (__nv_bfloat16*)(smb + 25088);
    __nv_bfloat16* phi = (__nv_bfloat16*)(smb);           // alias (after QK)
    __nv_bfloat16* plo = (__nv_bfloat16*)(smb + 10240);   // alias (after QK)

    const int bh = blockIdx.x;
    const int b  = bh >> 3;
    const int h  = bh & 7;
    const int tid  = threadIdx.x;
    const int lane = tid & 31;
    const int warp = tid >> 5;
    const int g  = lane >> 2, tg = lane & 3;
    const int m0 = warp * 16;
    const int r0 = m0 + g, r1 = r0 + 8;

    const size_t base = (size_t)bh * WIN * HD;
    const float ls = __expf(fminf(logit_scale[h], 4.6051701859880914f));

    {
        const int row = tid >> 1;
        const int d0  = (tid & 1) * 16;
        float qv[16];
        #pragma unroll
        for (int i = 0; i < 4; i++)
            *(float4*)&qv[4 * i] = *(const float4*)&g_q[base + row * HD + d0 + 4 * i];
        float s = 0.f;
        #pragma unroll
        for (int i = 0; i < 16; i++) s += qv[i] * qv[i];
        s += __shfl_xor_sync(0xffffffffu, s, 1);
        float inv = ls / fmaxf(sqrtf(s), 1e-12f);
        #pragma unroll
        for (int i = 0; i < 16; i += 2) {
            const float x0 = qv[i] * inv, x1 = qv[i + 1] * inv;
            const float h0 = bf16hi(x0), h1 = bf16hi(x1);
            *(uint32_t*)&qhi[row * QP + d0 + i] = pack_bf16(h0, h1);
            *(uint32_t*)&qlo[row * QP + d0 + i] = pack_bf16(x0 - h0, x1 - h1);
        }
        float kv[16];
        #pragma unroll
        for (int i = 0; i < 4; i++)
            *(float4*)&kv[4 * i] = *(const float4*)&g_k[base + row * HD + d0 + 4 * i];
        s = 0.f;
        #pragma unroll
        for (int i = 0; i < 16; i++) s += kv[i] * kv[i];
        s += __shfl_xor_sync(0xffffffffu, s, 1);
        inv = 1.0f / fmaxf(sqrtf(s), 1e-12f);
        #pragma unroll
        for (int i = 0; i < 16; i += 2) {
            const float x0 = kv[i] * inv, x1 = kv[i + 1] * inv;
            const float h0 = bf16hi(x0), h1 = bf16hi(x1);
            *(uint32_t*)&khi[row * QP + d0 + i] = pack_bf16(h0, h1);
            *(uint32_t*)&klo[row * QP + d0 + i] = pack_bf16(x0 - h0, x1 - h1);
        }
        #pragma unroll
        for (int i = 0; i < 4; i++) {
            const int idx = tid + 128 * i;
            const int n = idx >> 3, c = (idx & 7) * 4;
            float4 v = *(const float4*)&g_v[base + n * HD + c];
            float vv[4] = {v.x, v.y, v.z, v.w};
            #pragma unroll
            for (int j = 0; j < 4; j++) {
                const float hf = bf16hi(vv[j]);
                vth[(c + j) * VTP + n] = __float2bfloat16_rn(hf);
                vtl[(c + j) * VTP + n] = __float2bfloat16_rn(vv[j] - hf);
            }
        }
    }
    __syncthreads();

    float2 bm0[8], bm1[8];
    {
        const float* bm = g_bm + ((size_t)((b & 255) * 8 + h) << 12);
        #pragma unroll
        for (int an = 0; an < 8; an++) {
            const int c = an * 8 + 2 * tg;
            bm0[an] = *(const float2*)&bm[r0 * 64 + c];
            bm1[an] = *(const float2*)&bm[r1 * 64 + c];
        }
    }

    float acc[8][4] = {};
    #pragma unroll
    for (int kst = 0; kst < 2; kst++) {
        const int kb = kst * 16;
        unsigned ah[4], al[4];
        ah[0] = *(uint32_t*)&qhi[(m0 + g)     * QP + kb + 2 * tg];
        ah[1] = *(uint32_t*)&qhi[(m0 + g + 8) * QP + kb + 2 * tg];
        ah[2] = *(uint32_t*)&qhi[(m0 + g)     * QP + kb + 2 * tg + 8];
        ah[3] = *(uint32_t*)&qhi[(m0 + g + 8) * QP + kb + 2 * tg + 8];
        al[0] = *(uint32_t*)&qlo[(m0 + g)     * QP + kb + 2 * tg];
        al[1] = *(uint32_t*)&qlo[(m0 + g + 8) * QP + kb + 2 * tg];
        al[2] = *(uint32_t*)&qlo[(m0 + g)     * QP + kb + 2 * tg + 8];
        al[3] = *(uint32_t*)&qlo[(m0 + g + 8) * QP + kb + 2 * tg + 8];
        #pragma unroll
        for (int an = 0; an < 8; an++) {
            const int nr = an * 8;
            unsigned bh0 = *(uint32_t*)&khi[(nr + g) * QP + kb + 2 * tg];
            unsigned bh1 = *(uint32_t*)&khi[(nr + g) * QP + kb + 2 * tg + 8];
            unsigned bl0 = *(uint32_t*)&klo[(nr + g) * QP + kb + 2 * tg];
            unsigned bl1 = *(uint32_t*)&klo[(nr + g) * QP + kb + 2 * tg + 8];
            mma_bf16(acc[an], ah[0], ah[1], ah[2], ah[3], bh0, bh1);
            mma_bf16(acc[an], ah[0], ah[1], ah[2], ah[3], bl0, bl1);
            mma_bf16(acc[an], al[0], al[1], al[2], al[3], bh0, bh1);
        }
    }
    __syncthreads();

    {
        float m0v = -1e30f, m1v = -1e30f;
        #pragma unroll
        for (int an = 0; an < 8; an++) {
            acc[an][0] += bm0[an].x; acc[an][1] += bm0[an].y;
            acc[an][2] += bm1[an].x; acc[an][3] += bm1[an].y;
            m0v = fmaxf(m0v, fmaxf(acc[an][0], acc[an][1]));
            m1v = fmaxf(m1v, fmaxf(acc[an][2], acc[an][3]));
        }
        m0v = fmaxf(m0v, __shfl_xor_sync(0xffffffffu, m0v, 1));
        m0v = fmaxf(m0v, __shfl_xor_sync(0xffffffffu, m0v, 2));
        m1v = fmaxf(m1v, __shfl_xor_sync(0xffffffffu, m1v, 1));
        m1v = fmaxf(m1v, __shfl_xor_sync(0xffffffffu, m1v, 2));
        float s0 = 0.f, s1 = 0.f;
        #pragma unroll
        for (int an = 0; an < 8; an++) {
            acc[an][0] = __expf(acc[an][0] - m0v); s0 += acc[an][0];
            acc[an][1] = __expf(acc[an][1] - m0v); s0 += acc[an][1];
            acc[an][2] = __expf(acc[an][2] - m1v); s1 += acc[an][2];
            acc[an][3] = __expf(acc[an][3] - m1v); s1 += acc[an][3];
        }
        s0 += __shfl_xor_sync(0xffffffffu, s0, 1);
        s0 += __shfl_xor_sync(0xffffffffu, s0, 2);
        s1 += __shfl_xor_sync(0xffffffffu, s1, 1);
        s1 += __shfl_xor_sync(0xffffffffu, s1, 2);
        const float i0 = 1.0f / s0, i1 = 1.0f / s1;
        #pragma unroll
        for (int an = 0; an < 8; an++) {
            const int c = an * 8 + 2 * tg;
            const float p00 = acc[an][0] * i0, p01 = acc[an][1] * i0;
            const float p10 = acc[an][2] * i1, p11 = acc[an][3] * i1;
            const float h00 = bf16hi(p00), h01 = bf16hi(p01);
            const float h10 = bf16hi(p10), h11 = bf16hi(p11);
            *(uint32_t*)&phi[r0 * PPB + c] = pack_bf16(h00, h01);
            *(uint32_t*)&phi[r1 * PPB + c] = pack_bf16(h10, h11);
            *(uint32_t*)&plo[r0 * PPB + c] = pack_bf16(p00 - h00, p01 - h01);
            *(uint32_t*)&plo[r1 * PPB + c] = pack_bf16(p10 - h10, p11 - h11);
        }
    }
    __syncwarp();

    float oacc[4][4] = {};
    #pragma unroll
    for (int kst = 0; kst < 4; kst++) {
        const int kb = kst * 16;
        unsigned ah[4], al[4];
        ah[0] = *(uint32_t*)&phi[(m0 + g)     * PPB + kb + 2 * tg];
        ah[1] = *(uint32_t*)&phi[(m0 + g + 8) * PPB + kb + 2 * tg];
        ah[2] = *(uint32_t*)&phi[(m0 + g)     * PPB + kb + 2 * tg + 8];
        ah[3] = *(uint32_t*)&phi[(m0 + g + 8) * PPB + kb + 2 * tg + 8];
        al[0] = *(uint32_t*)&plo[(m0 + g)     * PPB + kb + 2 * tg];
        al[1] = *(uint32_t*)&plo[(m0 + g + 8) * PPB + kb + 2 * tg];
        al[2] = *(uint32_t*)&plo[(m0 + g)     * PPB + kb + 2 * tg + 8];
        al[3] = *(uint32_t*)&plo[(m0 + g + 8) * PPB + kb + 2 * tg + 8];
        #pragma unroll
        for (int dn = 0; dn < 4; dn++) {
            const int nn = dn * 8;
            unsigned bh0 = *(uint32_t*)&vth[(nn + g) * VTP + kb + 2 * tg];
            unsigned bh1 = *(uint32_t*)&vth[(nn + g) * VTP + kb + 2 * tg + 8];
            unsigned bl0 = *(uint32_t*)&vtl[(nn + g) * VTP + kb + 2 * tg];
            unsigned bl1 = *(uint32_t*)&vtl[(nn + g) * VTP + kb + 2 * tg + 8];
            mma_bf16(oacc[dn], ah[0], ah[1], ah[2], ah[3], bh0, bh1);
            mma_bf16(oacc[dn], ah[0], ah[1], ah[2], ah[3], bl0, bl1);
            mma_bf16(oacc[dn], al[0], al[1], al[2], al[3], bh0, bh1);
        }
    }

    float* aop = g_ao + (size_t)b * WIN * DIM + h * HD;
    #pragma unroll
    for (int dn = 0; dn < 4; dn++) {
        const int c = dn * 8 + 2 * tg;
        *(float2*)&aop[(size_t)r0 * DIM + c] = make_float2(oacc[dn][0], oacc[dn][1]);
        *(float2*)&aop[(size_t)r1 * DIM + c] = make_float2(oacc[dn][2], oacc[dn][3]);
    }
}

// ---------------------------------------------------------------------------
extern "C" void kernel_launch(void* const* d_in, const int* in_sizes, int n_in,
                              void* d_out, int out_size)
{
    const float* x        = (const float*)d_in[0];
    const float* mask     = (const float*)d_in[1];
    const float* qkv_w    = (const float*)d_in[2];
    const float* qkv_b    = (const float*)d_in[3];
    const float* proj_w   = (const float*)d_in[4];
    const float* proj_b   = (const float*)d_in[5];
    const float* lscale   = (const float*)d_in[6];
    const float* btable   = (const float*)d_in[7];
    const int*   rpi      = (const int*)d_in[8];
    float* out = (float*)d_out;

    cudaFuncSetAttribute(attn_kernel, cudaFuncAttributeMaxDynamicSharedMemorySize,
                         ATTN_SMEM_BYTES);

    // 0) bias+mask tables
    bm_pre<<<32768, 256>>>(btable, rpi, mask);
    // 1) QKV projection (fp16 tensor cores): C[131072 x 768]
    {
        dim3 grid(QKV_N / 128, MROWS / 128);
        mma_gemm<true><<<grid, 128>>>(x, qkv_w, qkv_b, nullptr);
    }
    // 2) Attention per (window, head)
    {
        attn_kernel<<<NWIN * HEADS, 128, ATTN_SMEM_BYTES>>>(lscale);
    }
    // 3) Output projection (fp16 tensor cores): C[131072 x 256]
    {
        float* ao = nullptr;
        cudaGetSymbolAddress((void**)&ao, g_ao);
        dim3 grid(DIM / 128, MROWS / 128);
        mma_gemm<false><<<grid, 128>>>(ao, proj_w, proj_b, out);
    }
}

// round 12
// speedup vs baseline: 1.6622x; 1.1702x over previous
#include <cuda_runtime.h>
#include <cuda_bf16.h>
#include <cuda_fp16.h>
#include <cstdint>

#define NWIN   2048
#define WIN    64
#define DIM    256
#define HEADS  8
#define HD     32
#define QKV_N  768
#define MROWS  (NWIN*WIN)  // 131072

__device__ float g_q[(size_t)NWIN*HEADS*WIN*HD];
__device__ float g_k[(size_t)NWIN*HEADS*WIN*HD];
__device__ float g_v[(size_t)NWIN*HEADS*WIN*HD];
__device__ float g_bm[(size_t)256*HEADS*WIN*WIN];
__device__ __half g_xh[(size_t)MROWS*DIM];     // fp16 x
__device__ __half g_aoh[(size_t)MROWS*DIM];    // fp16 attention output
__device__ __half g_wqh[QKV_N*DIM];
__device__ __half g_wph[DIM*DIM];

__device__ __forceinline__ uint32_t pack_bf16(float a, float b) {
    __nv_bfloat162 t = __floats2bfloat162_rn(a, b);
    return *(uint32_t*)&t;
}
__device__ __forceinline__ float bf16hi(float x) {
    return __bfloat162float(__float2bfloat16_rn(x));
}
__device__ __forceinline__ uint32_t pack_f16(float a, float b) {
    __half2 t = __floats2half2_rn(a, b);
    return *(uint32_t*)&t;
}

__device__ __forceinline__ void mma_bf16(float c[4],
                                         unsigned a0, unsigned a1, unsigned a2, unsigned a3,
                                         unsigned b0, unsigned b1) {
    asm volatile(
        "mma.sync.aligned.m16n8k16.row.col.f32.bf16.bf16.f32 "
        "{%0,%1,%2,%3}, {%4,%5,%6,%7}, {%8,%9}, {%0,%1,%2,%3};"
        : "+f"(c[0]), "+f"(c[1]), "+f"(c[2]), "+f"(c[3])
        : "r"(a0), "r"(a1), "r"(a2), "r"(a3), "r"(b0), "r"(b1));
}

__device__ __forceinline__ void mma_f16(float c[4],
                                        unsigned a0, unsigned a1, unsigned a2, unsigned a3,
                                        unsigned b0, unsigned b1) {
    asm volatile(
        "mma.sync.aligned.m16n8k16.row.col.f32.f16.f16.f32 "
        "{%0,%1,%2,%3}, {%4,%5,%6,%7}, {%8,%9}, {%0,%1,%2,%3};"
        : "+f"(c[0]), "+f"(c[1]), "+f"(c[2]), "+f"(c[3])
        : "r"(a0), "r"(a1), "r"(a2), "r"(a3), "r"(b0), "r"(b1));
}

__device__ __forceinline__ void cp16(uint32_t dst, const void* src) {
    asm volatile("cp.async.cg.shared.global [%0], [%1], 16;" :: "r"(dst), "l"(src));
}

// ---------------------------------------------------------------------------
// fp32 -> fp16 conversion pre-pass
// ---------------------------------------------------------------------------
__global__ void conv_f16(const float* __restrict__ src, __half* __restrict__ dst, int n4)
{
    const int i = blockIdx.x * 256 + threadIdx.x;
    if (i < n4) {
        float4 v = ((const float4*)src)[i];
        ((uint2*)dst)[i] = make_uint2(pack_f16(v.x, v.y), pack_f16(v.z, v.w));
    }
}

// ---------------------------------------------------------------------------
// bias+mask tables
// ---------------------------------------------------------------------------
__global__ void bm_pre(const float* __restrict__ bt, const int* __restrict__ rpi,
                       const float* __restrict__ mask)
{
    const int idx = blockIdx.x * 256 + threadIdx.x;
    const int e = idx & 4095;
    const int h = (idx >> 12) & 7;
    const int w = idx >> 15;
    g_bm[idx] = bt[rpi[e] * HEADS + h] + mask[w * 4096 + e];
}

// ---------------------------------------------------------------------------
// GEMM: C = A @ W^T + bias, K=256, fp16 inputs (pre-converted), fp32 accum.
// Block 128x128, 4 warps, warp 64x64, BK=32, cp.async 2-stage double buffer.
// pitch 40 halves -> fragment LDS bank = (20*row + tg) mod 32: conflict-free.
// ---------------------------------------------------------------------------
#define GP 40

template<bool QKV>
__global__ void __launch_bounds__(128, 2) mma_gemm(const __half* __restrict__ A,
                                                   const __half* __restrict__ W,
                                                   const float* __restrict__ bias,
                                                   float* __restrict__ out)
{
    const int K = DIM;
    __shared__ __half As[2][128 * GP];
    __shared__ __half Bs[2][128 * GP];
    uint32_t sA[2], sB[2];
    #pragma unroll
    for (int s = 0; s < 2; s++) {
        sA[s] = (uint32_t)__cvta_generic_to_shared(&As[s][0]);
        sB[s] = (uint32_t)__cvta_generic_to_shared(&Bs[s][0]);
    }

    const int rowBase = blockIdx.y * 128;
    const int colBase = blockIdx.x * 128;
    const int tid  = threadIdx.x;
    const int lane = tid & 31;
    const int warp = tid >> 5;
    const int warpM = warp >> 1;
    const int warpN = warp & 1;
    const int g  = lane >> 2;
    const int tg = lane & 3;
    const int m0 = warpM * 64;
    const int n0 = warpN * 64;

    const int lr = tid >> 2;            // 0..31 (+32*i)
    const int lc8 = (tid & 3) * 8;      // 0,8,16,24 halves

    auto issue = [&](int buf, int kb) {
        #pragma unroll
        for (int i = 0; i < 4; i++) {
            const int r = lr + 32 * i;
            const uint32_t off = (uint32_t)(r * GP + lc8) * 2;
            cp16(sA[buf] + off, &A[(size_t)(rowBase + r) * K + kb + lc8]);
            cp16(sB[buf] + off, &W[(size_t)(colBase + r) * K + kb + lc8]);
        }
        asm volatile("cp.async.commit_group;");
    };

    issue(0, 0);
    issue(1, 32);

    float acc[4][8][4] = {};

    for (int it = 0; it < 8; it++) {
        if (it == 7) asm volatile("cp.async.wait_group 0;");
        else         asm volatile("cp.async.wait_group 1;");
        __syncthreads();
        const __half* as = As[it & 1];
        const __half* bs = Bs[it & 1];

        #pragma unroll
        for (int ks = 0; ks < 2; ks++) {
            const int k0 = ks * 16;
            unsigned a[4][4];
            #pragma unroll
            for (int am = 0; am < 4; am++) {
                const int mr = m0 + am * 16;
                a[am][0] = *(const uint32_t*)&as[(mr + g)     * GP + k0 + 2 * tg];
                a[am][1] = *(const uint32_t*)&as[(mr + g + 8) * GP + k0 + 2 * tg];
                a[am][2] = *(const uint32_t*)&as[(mr + g)     * GP + k0 + 2 * tg + 8];
                a[am][3] = *(const uint32_t*)&as[(mr + g + 8) * GP + k0 + 2 * tg + 8];
            }
            unsigned bf[8][2];
            #pragma unroll
            for (int an = 0; an < 8; an++) {
                const int nr = n0 + an * 8;
                bf[an][0] = *(const uint32_t*)&bs[(nr + g) * GP + k0 + 2 * tg];
                bf[an][1] = *(const uint32_t*)&bs[(nr + g) * GP + k0 + 2 * tg + 8];
            }
            #pragma unroll
            for (int am = 0; am < 4; am++)
                #pragma unroll
                for (int an = 0; an < 8; an++)
                    mma_f16(acc[am][an], a[am][0], a[am][1], a[am][2], a[am][3],
                            bf[an][0], bf[an][1]);
        }
        __syncthreads();
        if (it < 6) issue(it & 1, (it + 2) * 32);
    }

    #pragma unroll
    for (int am = 0; am < 4; am++) {
        #pragma unroll
        for (int an = 0; an < 8; an++) {
            const int col = colBase + n0 + an * 8 + 2 * tg;
            const float bi0 = bias[col], bi1 = bias[col + 1];
            #pragma unroll
            for (int half = 0; half < 2; half++) {
                const int row = rowBase + m0 + am * 16 + g + 8 * half;
                float2 v;
                v.x = acc[am][an][2 * half]     + bi0;
                v.y = acc[am][an][2 * half + 1] + bi1;
                if (QKV) {
                    const int b = row >> 6, n = row & 63;
                    const int which = col >> 8;
                    const int h = (col >> 5) & 7;
                    const int d = col & 31;
                    float* dst = (which == 0) ? g_q : (which == 1) ? g_k : g_v;
                    *(float2*)&dst[((((size_t)b * HEADS + h) * WIN) + n) * HD + d] = v;
                } else {
                    *(float2*)&out[(size_t)row * DIM + col] = v;
                }
            }
        }
    }
}

// ---------------------------------------------------------------------------
// Attention (round-9/11 proven): latency-lean, 3-term bf16, 128 threads.
// Epilogue writes fp16 g_aoh (consumed directly by proj GEMM).
// ---------------------------------------------------------------------------
#define QP  40
#define PPB 72
#define VTP 72
#define ATTN_SMEM_BYTES 29696

__global__ void __launch_bounds__(128) attn_kernel(const float* __restrict__ logit_scale)
{
    extern __shared__ char smb[];
    __nv_bfloat16* qhi = (__nv_bfloat16*)(smb);
    __nv_bfloat16* qlo = (__nv_bfloat16*)(smb + 5120);
    __nv_bfloat16* khi = (__nv_bfloat16*)(smb + 10240);
    __nv_bfloat16* klo = (__nv_bfloat16*)(smb + 15360);
    __nv_bfloat16* vth = (__nv_bfloat16*)(smb + 20480);
    __nv_bfloat16* vtl = (__nv_bfloat16*)(smb + 25088);
    __nv_bfloat16* phi = (__nv_bfloat16*)(smb);           // alias (after QK)
    __nv_bfloat16* plo = (__nv_bfloat16*)(smb + 10240);   // alias (after QK)

    const int bh = blockIdx.x;
    const int b  = bh >> 3;
    const int h  = bh & 7;
    const int tid  = threadIdx.x;
    const int lane = tid & 31;
    const int warp = tid >> 5;
    const int g  = lane >> 2, tg = lane & 3;
    const int m0 = warp * 16;
    const int r0 = m0 + g, r1 = r0 + 8;

    const size_t base = (size_t)bh * WIN * HD;
    const float ls = __expf(fminf(logit_scale[h], 4.6051701859880914f));

    {
        const int row = tid >> 1;
        const int d0  = (tid & 1) * 16;
        float qv[16];
        #pragma unroll
        for (int i = 0; i < 4; i++)
            *(float4*)&qv[4 * i] = *(const float4*)&g_q[base + row * HD + d0 + 4 * i];
        float s = 0.f;
        #pragma unroll
        for (int i = 0; i < 16; i++) s += qv[i] * qv[i];
        s += __shfl_xor_sync(0xffffffffu, s, 1);
        float inv = ls / fmaxf(sqrtf(s), 1e-12f);
        #pragma unroll
        for (int i = 0; i < 16; i += 2) {
            const float x0 = qv[i] * inv, x1 = qv[i + 1] * inv;
            const float h0 = bf16hi(x0), h1 = bf16hi(x1);
            *(uint32_t*)&qhi[row * QP + d0 + i] = pack_bf16(h0, h1);
            *(uint32_t*)&qlo[row * QP + d0 + i] = pack_bf16(x0 - h0, x1 - h1);
        }
        float kv[16];
        #pragma unroll
        for (int i = 0; i < 4; i++)
            *(float4*)&kv[4 * i] = *(const float4*)&g_k[base + row * HD + d0 + 4 * i];
        s = 0.f;
        #pragma unroll
        for (int i = 0; i < 16; i++) s += kv[i] * kv[i];
        s += __shfl_xor_sync(0xffffffffu, s, 1);
        inv = 1.0f / fmaxf(sqrtf(s), 1e-12f);
        #pragma unroll
        for (int i = 0; i < 16; i += 2) {
            const float x0 = kv[i] * inv, x1 = kv[i + 1] * inv;
            const float h0 = bf16hi(x0), h1 = bf16hi(x1);
            *(uint32_t*)&khi[row * QP + d0 + i] = pack_bf16(h0, h1);
            *(uint32_t*)&klo[row * QP + d0 + i] = pack_bf16(x0 - h0, x1 - h1);
        }
        #pragma unroll
        for (int i = 0; i < 4; i++) {
            const int idx = tid + 128 * i;
            const int n = idx >> 3, c = (idx & 7) * 4;
            float4 v = *(const float4*)&g_v[base + n * HD + c];
            float vv[4] = {v.x, v.y, v.z, v.w};
            #pragma unroll
            for (int j = 0; j < 4; j++) {
                const float hf = bf16hi(vv[j]);
                vth[(c + j) * VTP + n] = __float2bfloat16_rn(hf);
                vtl[(c + j) * VTP + n] = __float2bfloat16_rn(vv[j] - hf);
            }
        }
    }
    __syncthreads();

    float2 bm0[8], bm1[8];
    {
        const float* bm = g_bm + ((size_t)((b & 255) * 8 + h) << 12);
        #pragma unroll
        for (int an = 0; an < 8; an++) {
            const int c = an * 8 + 2 * tg;
            bm0[an] = *(const float2*)&bm[r0 * 64 + c];
            bm1[an] = *(const float2*)&bm[r1 * 64 + c];
        }
    }

    float acc[8][4] = {};
    #pragma unroll
    for (int kst = 0; kst < 2; kst++) {
        const int kb = kst * 16;
        unsigned ah[4], al[4];
        ah[0] = *(uint32_t*)&qhi[(m0 + g)     * QP + kb + 2 * tg];
        ah[1] = *(uint32_t*)&qhi[(m0 + g + 8) * QP + kb + 2 * tg];
        ah[2] = *(uint32_t*)&qhi[(m0 + g)     * QP + kb + 2 * tg + 8];
        ah[3] = *(uint32_t*)&qhi[(m0 + g + 8) * QP + kb + 2 * tg + 8];
        al[0] = *(uint32_t*)&qlo[(m0 + g)     * QP + kb + 2 * tg];
        al[1] = *(uint32_t*)&qlo[(m0 + g + 8) * QP + kb + 2 * tg];
        al[2] = *(uint32_t*)&qlo[(m0 + g)     * QP + kb + 2 * tg + 8];
        al[3] = *(uint32_t*)&qlo[(m0 + g + 8) * QP + kb + 2 * tg + 8];
        #pragma unroll
        for (int an = 0; an < 8; an++) {
            const int nr = an * 8;
            unsigned bh0 = *(uint32_t*)&khi[(nr + g) * QP + kb + 2 * tg];
            unsigned bh1 = *(uint32_t*)&khi[(nr + g) * QP + kb + 2 * tg + 8];
            unsigned bl0 = *(uint32_t*)&klo[(nr + g) * QP + kb + 2 * tg];
            unsigned bl1 = *(uint32_t*)&klo[(nr + g) * QP + kb + 2 * tg + 8];
            mma_bf16(acc[an], ah[0], ah[1], ah[2], ah[3], bh0, bh1);
            mma_bf16(acc[an], ah[0], ah[1], ah[2], ah[3], bl0, bl1);
            mma_bf16(acc[an], al[0], al[1], al[2], al[3], bh0, bh1);
        }
    }
    __syncthreads();

    {
        float m0v = -1e30f, m1v = -1e30f;
        #pragma unroll
        for (int an = 0; an < 8; an++) {
            acc[an][0] += bm0[an].x; acc[an][1] += bm0[an].y;
            acc[an][2] += bm1[an].x; acc[an][3] += bm1[an].y;
            m0v = fmaxf(m0v, fmaxf(acc[an][0], acc[an][1]));
            m1v = fmaxf(m1v, fmaxf(acc[an][2], acc[an][3]));
        }
        m0v = fmaxf(m0v, __shfl_xor_sync(0xffffffffu, m0v, 1));
        m0v = fmaxf(m0v, __shfl_xor_sync(0xffffffffu, m0v, 2));
        m1v = fmaxf(m1v, __shfl_xor_sync(0xffffffffu, m1v, 1));
        m1v = fmaxf(m1v, __shfl_xor_sync(0xffffffffu, m1v, 2));
        float s0 = 0.f, s1 = 0.f;
        #pragma unroll
        for (int an = 0; an < 8; an++) {
            acc[an][0] = __expf(acc[an][0] - m0v); s0 += acc[an][0];
            acc[an][1] = __expf(acc[an][1] - m0v); s0 += acc[an][1];
            acc[an][2] = __expf(acc[an][2] - m1v); s1 += acc[an][2];
            acc[an][3] = __expf(acc[an][3] - m1v); s1 += acc[an][3];
        }
        s0 += __shfl_xor_sync(0xffffffffu, s0, 1);
        s0 += __shfl_xor_sync(0xffffffffu, s0, 2);
        s1 += __shfl_xor_sync(0xffffffffu, s1, 1);
        s1 += __shfl_xor_sync(0xffffffffu, s1, 2);
        const float i0 = 1.0f / s0, i1 = 1.0f / s1;
        #pragma unroll
        for (int an = 0; an < 8; an++) {
            const int c = an * 8 + 2 * tg;
            const float p00 = acc[an][0] * i0, p01 = acc[an][1] * i0;
            const float p10 = acc[an][2] * i1, p11 = acc[an][3] * i1;
            const float h00 = bf16hi(p00), h01 = bf16hi(p01);
            const float h10 = bf16hi(p10), h11 = bf16hi(p11);
            *(uint32_t*)&phi[r0 * PPB + c] = pack_bf16(h00, h01);
            *(uint32_t*)&phi[r1 * PPB + c] = pack_bf16(h10, h11);
            *(uint32_t*)&plo[r0 * PPB + c] = pack_bf16(p00 - h00, p01 - h01);
            *(uint32_t*)&plo[r1 * PPB + c] = pack_bf16(p10 - h10, p11 - h11);
        }
    }
    __syncwarp();

    float oacc[4][4] = {};
    #pragma unroll
    for (int kst = 0; kst < 4; kst++) {
        const int kb = kst * 16;
        unsigned ah[4], al[4];
        ah[0] = *(uint32_t*)&phi[(m0 + g)     * PPB + kb + 2 * tg];
        ah[1] = *(uint32_t*)&phi[(m0 + g + 8) * PPB + kb + 2 * tg];
        ah[2] = *(uint32_t*)&phi[(m0 + g)     * PPB + kb + 2 * tg + 8];
        ah[3] = *(uint32_t*)&phi[(m0 + g + 8) * PPB + kb + 2 * tg + 8];
        al[0] = *(uint32_t*)&plo[(m0 + g)     * PPB + kb + 2 * tg];
        al[1] = *(uint32_t*)&plo[(m0 + g + 8) * PPB + kb + 2 * tg];
        al[2] = *(uint32_t*)&plo[(m0 + g)     * PPB + kb + 2 * tg + 8];
        al[3] = *(uint32_t*)&plo[(m0 + g + 8) * PPB + kb + 2 * tg + 8];
        #pragma unroll
        for (int dn = 0; dn < 4; dn++) {
            const int nn = dn * 8;
            unsigned bh0 = *(uint32_t*)&vth[(nn + g) * VTP + kb + 2 * tg];
            unsigned bh1 = *(uint32_t*)&vth[(nn + g) * VTP + kb + 2 * tg + 8];
            unsigned bl0 = *(uint32_t*)&vtl[(nn + g) * VTP + kb + 2 * tg];
            unsigned bl1 = *(uint32_t*)&vtl[(nn + g) * VTP + kb + 2 * tg + 8];
            mma_bf16(oacc[dn], ah[0], ah[1], ah[2], ah[3], bh0, bh1);
            mma_bf16(oacc[dn], ah[0], ah[1], ah[2], ah[3], bl0, bl1);
            mma_bf16(oacc[dn], al[0], al[1], al[2], al[3], bh0, bh1);
        }
    }

    // write attention output directly as fp16 for the proj GEMM
    __half* aop = g_aoh + (size_t)b * WIN * DIM + h * HD;
    #pragma unroll
    for (int dn = 0; dn < 4; dn++) {
        const int c = dn * 8 + 2 * tg;
        *(uint32_t*)&aop[(size_t)r0 * DIM + c] = pack_f16(oacc[dn][0], oacc[dn][1]);
        *(uint32_t*)&aop[(size_t)r1 * DIM + c] = pack_f16(oacc[dn][2], oacc[dn][3]);
    }
}

// ---------------------------------------------------------------------------
extern "C" void kernel_launch(void* const* d_in, const int* in_sizes, int n_in,
                              void* d_out, int out_size)
{
    const float* x        = (const float*)d_in[0];
    const float* mask     = (const float*)d_in[1];
    const float* qkv_w    = (const float*)d_in[2];
    const float* qkv_b    = (const float*)d_in[3];
    const float* proj_w   = (const float*)d_in[4];
    const float* proj_b   = (const float*)d_in[5];
    const float* lscale   = (const float*)d_in[6];
    const float* btable   = (const float*)d_in[7];
    const int*   rpi      = (const int*)d_in[8];
    float* out = (float*)d_out;

    cudaFuncSetAttribute(attn_kernel, cudaFuncAttributeMaxDynamicSharedMemorySize,
                         ATTN_SMEM_BYTES);

    __half *xh, *wqh, *wph, *aoh;
    cudaGetSymbolAddress((void**)&xh,  g_xh);
    cudaGetSymbolAddress((void**)&wqh, g_wqh);
    cudaGetSymbolAddress((void**)&wph, g_wph);
    cudaGetSymbolAddress((void**)&aoh, g_aoh);

    // 0) pre-passes: fp16 conversion + bias/mask tables
    conv_f16<<<(MROWS*DIM/4 + 255)/256, 256>>>(x, xh, MROWS*DIM/4);
    conv_f16<<<(QKV_N*DIM/4 + 255)/256, 256>>>(qkv_w, wqh, QKV_N*DIM/4);
    conv_f16<<<(DIM*DIM/4 + 255)/256, 256>>>(proj_w, wph, DIM*DIM/4);
    bm_pre<<<32768, 256>>>(btable, rpi, mask);

    // 1) QKV projection (fp16 cp.async pipeline): C[131072 x 768]
    {
        dim3 grid(QKV_N / 128, MROWS / 128);
        mma_gemm<true><<<grid, 128>>>(xh, wqh, qkv_b, nullptr);
    }
    // 2) Attention per (window, head)
    {
        attn_kernel<<<NWIN * HEADS, 128, ATTN_SMEM_BYTES>>>(lscale);
    }
    // 3) Output projection: C[131072 x 256]
    {
        dim3 grid(DIM / 128, MROWS / 128);
        mma_gemm<false><<<grid, 128>>>(aoh, wph, proj_b, out);
    }
}

// round 13
// speedup vs baseline: 1.7224x; 1.0362x over previous
#include <cuda_runtime.h>
#include <cuda_bf16.h>
#include <cuda_fp16.h>
#include <cstdint>

#define NWIN   2048
#define WIN    64
#define DIM    256
#define HEADS  8
#define HD     32
#define QKV_N  768
#define MROWS  (NWIN*WIN)  // 131072

__device__ __half g_qh[(size_t)NWIN*HEADS*WIN*HD];
__device__ __half g_kh[(size_t)NWIN*HEADS*WIN*HD];
__device__ __half g_vh[(size_t)NWIN*HEADS*WIN*HD];
__device__ __half g_bmh[(size_t)256*HEADS*WIN*WIN];  // bias+mask tables, fp16 (16.7MB)
__device__ __half g_xh[(size_t)MROWS*DIM];
__device__ __half g_aoh[(size_t)MROWS*DIM];
__device__ __half g_wqh[QKV_N*DIM];
__device__ __half g_wph[DIM*DIM];

__device__ __forceinline__ uint32_t pack_bf16(float a, float b) {
    __nv_bfloat162 t = __floats2bfloat162_rn(a, b);
    return *(uint32_t*)&t;
}
__device__ __forceinline__ float bf16hi(float x) {
    return __bfloat162float(__float2bfloat16_rn(x));
}
__device__ __forceinline__ uint32_t pack_f16(float a, float b) {
    __half2 t = __floats2half2_rn(a, b);
    return *(uint32_t*)&t;
}

__device__ __forceinline__ void mma_bf16(float c[4],
                                         unsigned a0, unsigned a1, unsigned a2, unsigned a3,
                                         unsigned b0, unsigned b1) {
    asm volatile(
        "mma.sync.aligned.m16n8k16.row.col.f32.bf16.bf16.f32 "
        "{%0,%1,%2,%3}, {%4,%5,%6,%7}, {%8,%9}, {%0,%1,%2,%3};"
        : "+f"(c[0]), "+f"(c[1]), "+f"(c[2]), "+f"(c[3])
        : "r"(a0), "r"(a1), "r"(a2), "r"(a3), "r"(b0), "r"(b1));
}

__device__ __forceinline__ void mma_f16(float c[4],
                                        unsigned a0, unsigned a1, unsigned a2, unsigned a3,
                                        unsigned b0, unsigned b1) {
    asm volatile(
        "mma.sync.aligned.m16n8k16.row.col.f32.f16.f16.f32 "
        "{%0,%1,%2,%3}, {%4,%5,%6,%7}, {%8,%9}, {%0,%1,%2,%3};"
        : "+f"(c[0]), "+f"(c[1]), "+f"(c[2]), "+f"(c[3])
        : "r"(a0), "r"(a1), "r"(a2), "r"(a3), "r"(b0), "r"(b1));
}

__device__ __forceinline__ void cp16(uint32_t dst, const void* src) {
    asm volatile("cp.async.cg.shared.global [%0], [%1], 16;" :: "r"(dst), "l"(src));
}

// ---------------------------------------------------------------------------
// fp32 -> fp16 conversion pre-pass
// ---------------------------------------------------------------------------
__global__ void conv_f16(const float* __restrict__ src, __half* __restrict__ dst, int n4)
{
    const int i = blockIdx.x * 256 + threadIdx.x;
    if (i < n4) {
        float4 v = ((const float4*)src)[i];
        ((uint2*)dst)[i] = make_uint2(pack_f16(v.x, v.y), pack_f16(v.z, v.w));
    }
}

// ---------------------------------------------------------------------------
// bias+mask tables (fp16)
// ---------------------------------------------------------------------------
__global__ void bm_pre(const float* __restrict__ bt, const int* __restrict__ rpi,
                       const float* __restrict__ mask)
{
    const int idx = blockIdx.x * 256 + threadIdx.x;
    const int e = idx & 4095;
    const int h = (idx >> 12) & 7;
    const int w = idx >> 15;
    g_bmh[idx] = __float2half_rn(bt[rpi[e] * HEADS + h] + mask[w * 4096 + e]);
}

// ---------------------------------------------------------------------------
// GEMM: C = A @ W^T + bias, K=256, fp16 inputs, fp32 accum.
// Block 128x128, 4 warps, warp 64x64, BK=32, cp.async 2-stage double buffer.
// ---------------------------------------------------------------------------
#define GP 40

template<bool QKV>
__global__ void __launch_bounds__(128, 2) mma_gemm(const __half* __restrict__ A,
                                                   const __half* __restrict__ W,
                                                   const float* __restrict__ bias,
                                                   float* __restrict__ out)
{
    const int K = DIM;
    __shared__ __half As[2][128 * GP];
    __shared__ __half Bs[2][128 * GP];
    uint32_t sA[2], sB[2];
    #pragma unroll
    for (int s = 0; s < 2; s++) {
        sA[s] = (uint32_t)__cvta_generic_to_shared(&As[s][0]);
        sB[s] = (uint32_t)__cvta_generic_to_shared(&Bs[s][0]);
    }

    const int rowBase = blockIdx.y * 128;
    const int colBase = blockIdx.x * 128;
    const int tid  = threadIdx.x;
    const int lane = tid & 31;
    const int warp = tid >> 5;
    const int warpM = warp >> 1;
    const int warpN = warp & 1;
    const int g  = lane >> 2;
    const int tg = lane & 3;
    const int m0 = warpM * 64;
    const int n0 = warpN * 64;

    const int lr = tid >> 2;
    const int lc8 = (tid & 3) * 8;

    auto issue = [&](int buf, int kb) {
        #pragma unroll
        for (int i = 0; i < 4; i++) {
            const int r = lr + 32 * i;
            const uint32_t off = (uint32_t)(r * GP + lc8) * 2;
            cp16(sA[buf] + off, &A[(size_t)(rowBase + r) * K + kb + lc8]);
            cp16(sB[buf] + off, &W[(size_t)(colBase + r) * K + kb + lc8]);
        }
        asm volatile("cp.async.commit_group;");
    };

    issue(0, 0);
    issue(1, 32);

    float acc[4][8][4] = {};

    for (int it = 0; it < 8; it++) {
        if (it == 7) asm volatile("cp.async.wait_group 0;");
        else         asm volatile("cp.async.wait_group 1;");
        __syncthreads();
        const __half* as = As[it & 1];
        const __half* bs = Bs[it & 1];

        #pragma unroll
        for (int ks = 0; ks < 2; ks++) {
            const int k0 = ks * 16;
            unsigned a[4][4];
            #pragma unroll
            for (int am = 0; am < 4; am++) {
                const int mr = m0 + am * 16;
                a[am][0] = *(const uint32_t*)&as[(mr + g)     * GP + k0 + 2 * tg];
                a[am][1] = *(const uint32_t*)&as[(mr + g + 8) * GP + k0 + 2 * tg];
                a[am][2] = *(const uint32_t*)&as[(mr + g)     * GP + k0 + 2 * tg + 8];
                a[am][3] = *(const uint32_t*)&as[(mr + g + 8) * GP + k0 + 2 * tg + 8];
            }
            unsigned bf[8][2];
            #pragma unroll
            for (int an = 0; an < 8; an++) {
                const int nr = n0 + an * 8;
                bf[an][0] = *(const uint32_t*)&bs[(nr + g) * GP + k0 + 2 * tg];
                bf[an][1] = *(const uint32_t*)&bs[(nr + g) * GP + k0 + 2 * tg + 8];
            }
            #pragma unroll
            for (int am = 0; am < 4; am++)
                #pragma unroll
                for (int an = 0; an < 8; an++)
                    mma_f16(acc[am][an], a[am][0], a[am][1], a[am][2], a[am][3],
                            bf[an][0], bf[an][1]);
        }
        __syncthreads();
        if (it < 6) issue(it & 1, (it + 2) * 32);
    }

    #pragma unroll
    for (int am = 0; am < 4; am++) {
        #pragma unroll
        for (int an = 0; an < 8; an++) {
            const int col = colBase + n0 + an * 8 + 2 * tg;
            const float bi0 = bias[col], bi1 = bias[col + 1];
            #pragma unroll
            for (int half = 0; half < 2; half++) {
                const int row = rowBase + m0 + am * 16 + g + 8 * half;
                float2 v;
                v.x = acc[am][an][2 * half]     + bi0;
                v.y = acc[am][an][2 * half + 1] + bi1;
                if (QKV) {
                    // store q/k/v as fp16 scratch
                    const int b = row >> 6, n = row & 63;
                    const int which = col >> 8;
                    const int h = (col >> 5) & 7;
                    const int d = col & 31;
                    __half* dst = (which == 0) ? g_qh : (which == 1) ? g_kh : g_vh;
                    *(uint32_t*)&dst[((((size_t)b * HEADS + h) * WIN) + n) * HD + d] =
                        pack_f16(v.x, v.y);
                } else {
                    *(float2*)&out[(size_t)row * DIM + col] = v;
                }
            }
        }
    }
}

// ---------------------------------------------------------------------------
// Attention (round-9 structure), fp16 q/k/v/bm inputs, 3-term bf16 MMA.
// ---------------------------------------------------------------------------
#define QP  40
#define PPB 72
#define VTP 72
#define ATTN_SMEM_BYTES 29696

__global__ void __launch_bounds__(128) attn_kernel(const float* __restrict__ logit_scale)
{
    extern __shared__ char smb[];
    __nv_bfloat16* qhi = (__nv_bfloat16*)(smb);
    __nv_bfloat16* qlo = (__nv_bfloat16*)(smb + 5120);
    __nv_bfloat16* khi = (__nv_bfloat16*)(smb + 10240);
    __nv_bfloat16* klo = (__nv_bfloat16*)(smb + 15360);
    __nv_bfloat16* vth = (__nv_bfloat16*)(smb + 20480);
    __nv_bfloat16* vtl = (__nv_bfloat16*)(smb + 25088);
    __nv_bfloat16* phi = (__nv_bfloat16*)(smb);           // alias (after QK)
    __nv_bfloat16* plo = (__nv_bfloat16*)(smb + 10240);   // alias (after QK)

    const int bh = blockIdx.x;
    const int b  = bh >> 3;
    const int h  = bh & 7;
    const int tid  = threadIdx.x;
    const int lane = tid & 31;
    const int warp = tid >> 5;
    const int g  = lane >> 2, tg = lane & 3;
    const int m0 = warp * 16;
    const int r0 = m0 + g, r1 = r0 + 8;

    const size_t base = (size_t)bh * WIN * HD;
    const float ls = __expf(fminf(logit_scale[h], 4.6051701859880914f));

    // Phase 0: q/k half-row per thread (fp16 loads), norm via shfl; v transpose
    {
        const int row = tid >> 1;
        const int d0  = (tid & 1) * 16;
        float qv[16];
        {
            const __half2* qp = (const __half2*)&g_qh[base + row * HD + d0];
            #pragma unroll
            for (int i = 0; i < 8; i++) {
                float2 f = __half22float2(qp[i]);
                qv[2 * i] = f.x; qv[2 * i + 1] = f.y;
            }
        }
        float s = 0.f;
        #pragma unroll
        for (int i = 0; i < 16; i++) s += qv[i] * qv[i];
        s += __shfl_xor_sync(0xffffffffu, s, 1);
        float inv = ls / fmaxf(sqrtf(s), 1e-12f);
        #pragma unroll
        for (int i = 0; i < 16; i += 2) {
            const float x0 = qv[i] * inv, x1 = qv[i + 1] * inv;
            const float h0 = bf16hi(x0), h1 = bf16hi(x1);
            *(uint32_t*)&qhi[row * QP + d0 + i] = pack_bf16(h0, h1);
            *(uint32_t*)&qlo[row * QP + d0 + i] = pack_bf16(x0 - h0, x1 - h1);
        }
        float kv[16];
        {
            const __half2* kp = (const __half2*)&g_kh[base + row * HD + d0];
            #pragma unroll
            for (int i = 0; i < 8; i++) {
                float2 f = __half22float2(kp[i]);
                kv[2 * i] = f.x; kv[2 * i + 1] = f.y;
            }
        }
        s = 0.f;
        #pragma unroll
        for (int i = 0; i < 16; i++) s += kv[i] * kv[i];
        s += __shfl_xor_sync(0xffffffffu, s, 1);
        inv = 1.0f / fmaxf(sqrtf(s), 1e-12f);
        #pragma unroll
        for (int i = 0; i < 16; i += 2) {
            const float x0 = kv[i] * inv, x1 = kv[i + 1] * inv;
            const float h0 = bf16hi(x0), h1 = bf16hi(x1);
            *(uint32_t*)&khi[row * QP + d0 + i] = pack_bf16(h0, h1);
            *(uint32_t*)&klo[row * QP + d0 + i] = pack_bf16(x0 - h0, x1 - h1);
        }
        #pragma unroll
        for (int i = 0; i < 4; i++) {
            const int idx = tid + 128 * i;
            const int n = idx >> 3, c = (idx & 7) * 4;
            const __half2* vp = (const __half2*)&g_vh[base + n * HD + c];
            float2 f01 = __half22float2(vp[0]);
            float2 f23 = __half22float2(vp[1]);
            float vv[4] = {f01.x, f01.y, f23.x, f23.y};
            #pragma unroll
            for (int j = 0; j < 4; j++) {
                const float hf = bf16hi(vv[j]);
                vth[(c + j) * VTP + n] = __float2bfloat16_rn(hf);
                vtl[(c + j) * VTP + n] = __float2bfloat16_rn(vv[j] - hf);
            }
        }
    }
    __syncthreads();

    // Prefetch bias+mask (fp16) into registers
    float2 bm0[8], bm1[8];
    {
        const __half* bm = g_bmh + ((size_t)((b & 255) * 8 + h) << 12);
        #pragma unroll
        for (int an = 0; an < 8; an++) {
            const int c = an * 8 + 2 * tg;
            bm0[an] = __half22float2(*(const __half2*)&bm[r0 * 64 + c]);
            bm1[an] = __half22float2(*(const __half2*)&bm[r1 * 64 + c]);
        }
    }

    // QK^T, 3-term bf16
    float acc[8][4] = {};
    #pragma unroll
    for (int kst = 0; kst < 2; kst++) {
        const int kb = kst * 16;
        unsigned ah[4], al[4];
        ah[0] = *(uint32_t*)&qhi[(m0 + g)     * QP + kb + 2 * tg];
        ah[1] = *(uint32_t*)&qhi[(m0 + g + 8) * QP + kb + 2 * tg];
        ah[2] = *(uint32_t*)&qhi[(m0 + g)     * QP + kb + 2 * tg + 8];
        ah[3] = *(uint32_t*)&qhi[(m0 + g + 8) * QP + kb + 2 * tg + 8];
        al[0] = *(uint32_t*)&qlo[(m0 + g)     * QP + kb + 2 * tg];
        al[1] = *(uint32_t*)&qlo[(m0 + g + 8) * QP + kb + 2 * tg];
        al[2] = *(uint32_t*)&qlo[(m0 + g)     * QP + kb + 2 * tg + 8];
        al[3] = *(uint32_t*)&qlo[(m0 + g + 8) * QP + kb + 2 * tg + 8];
        #pragma unroll
        for (int an = 0; an < 8; an++) {
            const int nr = an * 8;
            unsigned bh0 = *(uint32_t*)&khi[(nr + g) * QP + kb + 2 * tg];
            unsigned bh1 = *(uint32_t*)&khi[(nr + g) * QP + kb + 2 * tg + 8];
            unsigned bl0 = *(uint32_t*)&klo[(nr + g) * QP + kb + 2 * tg];
            unsigned bl1 = *(uint32_t*)&klo[(nr + g) * QP + kb + 2 * tg + 8];
            mma_bf16(acc[an], ah[0], ah[1], ah[2], ah[3], bh0, bh1);
            mma_bf16(acc[an], ah[0], ah[1], ah[2], ah[3], bl0, bl1);
            mma_bf16(acc[an], al[0], al[1], al[2], al[3], bh0, bh1);
        }
    }
    __syncthreads();   // QK smem reads done before P writes alias q/k

    // bias+mask add + register softmax
    {
        float m0v = -1e30f, m1v = -1e30f;
        #pragma unroll
        for (int an = 0; an < 8; an++) {
            acc[an][0] += bm0[an].x; acc[an][1] += bm0[an].y;
            acc[an][2] += bm1[an].x; acc[an][3] += bm1[an].y;
            m0v = fmaxf(m0v, fmaxf(acc[an][0], acc[an][1]));
            m1v = fmaxf(m1v, fmaxf(acc[an][2], acc[an][3]));
        }
        m0v = fmaxf(m0v, __shfl_xor_sync(0xffffffffu, m0v, 1));
        m0v = fmaxf(m0v, __shfl_xor_sync(0xffffffffu, m0v, 2));
        m1v = fmaxf(m1v, __shfl_xor_sync(0xffffffffu, m1v, 1));
        m1v = fmaxf(m1v, __shfl_xor_sync(0xffffffffu, m1v, 2));
        float s0 = 0.f, s1 = 0.f;
        #pragma unroll
        for (int an = 0; an < 8; an++) {
            acc[an][0] = __expf(acc[an][0] - m0v); s0 += acc[an][0];
            acc[an][1] = __expf(acc[an][1] - m0v); s0 += acc[an][1];
            acc[an][2] = __expf(acc[an][2] - m1v); s1 += acc[an][2];
            acc[an][3] = __expf(acc[an][3] - m1v); s1 += acc[an][3];
        }
        s0 += __shfl_xor_sync(0xffffffffu, s0, 1);
        s0 += __shfl_xor_sync(0xffffffffu, s0, 2);
        s1 += __shfl_xor_sync(0xffffffffu, s1, 1);
        s1 += __shfl_xor_sync(0xffffffffu, s1, 2);
        const float i0 = 1.0f / s0, i1 = 1.0f / s1;
        #pragma unroll
        for (int an = 0; an < 8; an++) {
            const int c = an * 8 + 2 * tg;
            const float p00 = acc[an][0] * i0, p01 = acc[an][1] * i0;
            const float p10 = acc[an][2] * i1, p11 = acc[an][3] * i1;
            const float h00 = bf16hi(p00), h01 = bf16hi(p01);
            const float h10 = bf16hi(p10), h11 = bf16hi(p11);
            *(uint32_t*)&phi[r0 * PPB + c] = pack_bf16(h00, h01);
            *(uint32_t*)&phi[r1 * PPB + c] = pack_bf16(h10, h11);
            *(uint32_t*)&plo[r0 * PPB + c] = pack_bf16(p00 - h00, p01 - h01);
            *(uint32_t*)&plo[r1 * PPB + c] = pack_bf16(p10 - h10, p11 - h11);
        }
    }
    __syncwarp();

    // P @ V, 3-term bf16
    float oacc[4][4] = {};
    #pragma unroll
    for (int kst = 0; kst < 4; kst++) {
        const int kb = kst * 16;
        unsigned ah[4], al[4];
        ah[0] = *(uint32_t*)&phi[(m0 + g)     * PPB + kb + 2 * tg];
        ah[1] = *(uint32_t*)&phi[(m0 + g + 8) * PPB + kb + 2 * tg];
        ah[2] = *(uint32_t*)&phi[(m0 + g)     * PPB + kb + 2 * tg + 8];
        ah[3] = *(uint32_t*)&phi[(m0 + g + 8) * PPB + kb + 2 * tg + 8];
        al[0] = *(uint32_t*)&plo[(m0 + g)     * PPB + kb + 2 * tg];
        al[1] = *(uint32_t*)&plo[(m0 + g + 8) * PPB + kb + 2 * tg];
        al[2] = *(uint32_t*)&plo[(m0 + g)     * PPB + kb + 2 * tg + 8];
        al[3] = *(uint32_t*)&plo[(m0 + g + 8) * PPB + kb + 2 * tg + 8];
        #pragma unroll
        for (int dn = 0; dn < 4; dn++) {
            const int nn = dn * 8;
            unsigned bh0 = *(uint32_t*)&vth[(nn + g) * VTP + kb + 2 * tg];
            unsigned bh1 = *(uint32_t*)&vth[(nn + g) * VTP + kb + 2 * tg + 8];
            unsigned bl0 = *(uint32_t*)&vtl[(nn + g) * VTP + kb + 2 * tg];
            unsigned bl1 = *(uint32_t*)&vtl[(nn + g) * VTP + kb + 2 * tg + 8];
            mma_bf16(oacc[dn], ah[0], ah[1], ah[2], ah[3], bh0, bh1);
            mma_bf16(oacc[dn], ah[0], ah[1], ah[2], ah[3], bl0, bl1);
            mma_bf16(oacc[dn], al[0], al[1], al[2], al[3], bh0, bh1);
        }
    }

    __half* aop = g_aoh + (size_t)b * WIN * DIM + h * HD;
    #pragma unroll
    for (int dn = 0; dn < 4; dn++) {
        const int c = dn * 8 + 2 * tg;
        *(uint32_t*)&aop[(size_t)r0 * DIM + c] = pack_f16(oacc[dn][0], oacc[dn][1]);
        *(uint32_t*)&aop[(size_t)r1 * DIM + c] = pack_f16(oacc[dn][2], oacc[dn][3]);
    }
}

// ---------------------------------------------------------------------------
extern "C" void kernel_launch(void* const* d_in, const int* in_sizes, int n_in,
                              void* d_out, int out_size)
{
    const float* x        = (const float*)d_in[0];
    const float* mask     = (const float*)d_in[1];
    const float* qkv_w    = (const float*)d_in[2];
    const float* qkv_b    = (const float*)d_in[3];
    const float* proj_w   = (const float*)d_in[4];
    const float* proj_b   = (const float*)d_in[5];
    const float* lscale   = (const float*)d_in[6];
    const float* btable   = (const float*)d_in[7];
    const int*   rpi      = (const int*)d_in[8];
    float* out = (float*)d_out;

    cudaFuncSetAttribute(attn_kernel, cudaFuncAttributeMaxDynamicSharedMemorySize,
                         ATTN_SMEM_BYTES);

    __half *xh, *wqh, *wph, *aoh;
    cudaGetSymbolAddress((void**)&xh,  g_xh);
    cudaGetSymbolAddress((void**)&wqh, g_wqh);
    cudaGetSymbolAddress((void**)&wph, g_wph);
    cudaGetSymbolAddress((void**)&aoh, g_aoh);

    // 0) pre-passes
    conv_f16<<<(MROWS*DIM/4 + 255)/256, 256>>>(x, xh, MROWS*DIM/4);
    conv_f16<<<(QKV_N*DIM/4 + 255)/256, 256>>>(qkv_w, wqh, QKV_N*DIM/4);
    conv_f16<<<(DIM*DIM/4 + 255)/256, 256>>>(proj_w, wph, DIM*DIM/4);
    bm_pre<<<32768, 256>>>(btable, rpi, mask);

    // 1) QKV projection
    {
        dim3 grid(QKV_N / 128, MROWS / 128);
        mma_gemm<true><<<grid, 128>>>(xh, wqh, qkv_b, nullptr);
    }
    // 2) Attention per (window, head)
    {
        attn_kernel<<<NWIN * HEADS, 128, ATTN_SMEM_BYTES>>>(lscale);
    }
    // 3) Output projection
    {
        dim3 grid(DIM / 128, MROWS / 128);
        mma_gemm<false><<<grid, 128>>>(aoh, wph, proj_b, out);
    }
}

// round 14
// speedup vs baseline: 1.8195x; 1.0564x over previous
#include <cuda_runtime.h>
#include <cuda_bf16.h>
#include <cuda_fp16.h>
#include <cstdint>

#define NWIN   2048
#define WIN    64
#define DIM    256
#define HEADS  8
#define HD     32
#define QKV_N  768
#define MROWS  (NWIN*WIN)  // 131072

__device__ __half g_qh[(size_t)NWIN*HEADS*WIN*HD];
__device__ __half g_kh[(size_t)NWIN*HEADS*WIN*HD];
__device__ __half g_vh[(size_t)NWIN*HEADS*WIN*HD];
__device__ __half g_bmh[(size_t)256*HEADS*WIN*WIN];
__device__ __half g_xh[(size_t)MROWS*DIM];
__device__ __half g_aoh[(size_t)MROWS*DIM];
__device__ __half g_wqh[QKV_N*DIM];
__device__ __half g_wph[DIM*DIM];

__device__ __forceinline__ uint32_t pack_bf16(float a, float b) {
    __nv_bfloat162 t = __floats2bfloat162_rn(a, b);
    return *(uint32_t*)&t;
}
__device__ __forceinline__ float bf16hi(float x) {
    return __bfloat162float(__float2bfloat16_rn(x));
}
__device__ __forceinline__ uint32_t pack_f16(float a, float b) {
    __half2 t = __floats2half2_rn(a, b);
    return *(uint32_t*)&t;
}
__device__ __forceinline__ float f16hi(float x) {
    return __half2float(__float2half_rn(x));
}

__device__ __forceinline__ void mma_bf16(float c[4],
                                         unsigned a0, unsigned a1, unsigned a2, unsigned a3,
                                         unsigned b0, unsigned b1) {
    asm volatile(
        "mma.sync.aligned.m16n8k16.row.col.f32.bf16.bf16.f32 "
        "{%0,%1,%2,%3}, {%4,%5,%6,%7}, {%8,%9}, {%0,%1,%2,%3};"
        : "+f"(c[0]), "+f"(c[1]), "+f"(c[2]), "+f"(c[3])
        : "r"(a0), "r"(a1), "r"(a2), "r"(a3), "r"(b0), "r"(b1));
}

__device__ __forceinline__ void mma_f16(float c[4],
                                        unsigned a0, unsigned a1, unsigned a2, unsigned a3,
                                        unsigned b0, unsigned b1) {
    asm volatile(
        "mma.sync.aligned.m16n8k16.row.col.f32.f16.f16.f32 "
        "{%0,%1,%2,%3}, {%4,%5,%6,%7}, {%8,%9}, {%0,%1,%2,%3};"
        : "+f"(c[0]), "+f"(c[1]), "+f"(c[2]), "+f"(c[3])
        : "r"(a0), "r"(a1), "r"(a2), "r"(a3), "r"(b0), "r"(b1));
}

__device__ __forceinline__ void cp16(uint32_t dst, const void* src) {
    asm volatile("cp.async.cg.shared.global [%0], [%1], 16;" :: "r"(dst), "l"(src));
}

// ---------------------------------------------------------------------------
// fp32 -> fp16 conversion pre-pass
// ---------------------------------------------------------------------------
__global__ void conv_f16(const float* __restrict__ src, __half* __restrict__ dst, int n4)
{
    const int i = blockIdx.x * 256 + threadIdx.x;
    if (i < n4) {
        float4 v = ((const float4*)src)[i];
        ((uint2*)dst)[i] = make_uint2(pack_f16(v.x, v.y), pack_f16(v.z, v.w));
    }
}

// ---------------------------------------------------------------------------
// bias+mask tables (fp16), 4 elements per thread
// ---------------------------------------------------------------------------
__global__ void bm_pre(const float* __restrict__ bt, const int* __restrict__ rpi,
                       const float* __restrict__ mask)
{
    const int i4 = blockIdx.x * 256 + threadIdx.x;   // 0..2097151
    const int e = (i4 & 1023) * 4;
    const int h = (i4 >> 10) & 7;
    const int w = i4 >> 13;
    float4 m = *(const float4*)&mask[w * 4096 + e];
    const float b0 = bt[rpi[e]     * HEADS + h];
    const float b1 = bt[rpi[e + 1] * HEADS + h];
    const float b2 = bt[rpi[e + 2] * HEADS + h];
    const float b3 = bt[rpi[e + 3] * HEADS + h];
    *(uint2*)&g_bmh[(((size_t)(w * 8 + h)) << 12) + e] =
        make_uint2(pack_f16(b0 + m.x, b1 + m.y), pack_f16(b2 + m.z, b3 + m.w));
}

// ---------------------------------------------------------------------------
// GEMM (round-12 proven): fp16 cp.async 2-stage, block 128x128, warp 64x64.
// ---------------------------------------------------------------------------
#define GP 40

template<bool QKV>
__global__ void __launch_bounds__(128, 2) mma_gemm(const __half* __restrict__ A,
                                                   const __half* __restrict__ W,
                                                   const float* __restrict__ bias,
                                                   float* __restrict__ out)
{
    const int K = DIM;
    __shared__ __half As[2][128 * GP];
    __shared__ __half Bs[2][128 * GP];
    uint32_t sA[2], sB[2];
    #pragma unroll
    for (int s = 0; s < 2; s++) {
        sA[s] = (uint32_t)__cvta_generic_to_shared(&As[s][0]);
        sB[s] = (uint32_t)__cvta_generic_to_shared(&Bs[s][0]);
    }

    const int rowBase = blockIdx.y * 128;
    const int colBase = blockIdx.x * 128;
    const int tid  = threadIdx.x;
    const int lane = tid & 31;
    const int warp = tid >> 5;
    const int warpM = warp >> 1;
    const int warpN = warp & 1;
    const int g  = lane >> 2;
    const int tg = lane & 3;
    const int m0 = warpM * 64;
    const int n0 = warpN * 64;

    const int lr = tid >> 2;
    const int lc8 = (tid & 3) * 8;

    auto issue = [&](int buf, int kb) {
        #pragma unroll
        for (int i = 0; i < 4; i++) {
            const int r = lr + 32 * i;
            const uint32_t off = (uint32_t)(r * GP + lc8) * 2;
            cp16(sA[buf] + off, &A[(size_t)(rowBase + r) * K + kb + lc8]);
            cp16(sB[buf] + off, &W[(size_t)(colBase + r) * K + kb + lc8]);
        }
        asm volatile("cp.async.commit_group;");
    };

    issue(0, 0);
    issue(1, 32);

    float acc[4][8][4] = {};

    for (int it = 0; it < 8; it++) {
        if (it == 7) asm volatile("cp.async.wait_group 0;");
        else         asm volatile("cp.async.wait_group 1;");
        __syncthreads();
        const __half* as = As[it & 1];
        const __half* bs = Bs[it & 1];

        #pragma unroll
        for (int ks = 0; ks < 2; ks++) {
            const int k0 = ks * 16;
            unsigned a[4][4];
            #pragma unroll
            for (int am = 0; am < 4; am++) {
                const int mr = m0 + am * 16;
                a[am][0] = *(const uint32_t*)&as[(mr + g)     * GP + k0 + 2 * tg];
                a[am][1] = *(const uint32_t*)&as[(mr + g + 8) * GP + k0 + 2 * tg];
                a[am][2] = *(const uint32_t*)&as[(mr + g)     * GP + k0 + 2 * tg + 8];
                a[am][3] = *(const uint32_t*)&as[(mr + g + 8) * GP + k0 + 2 * tg + 8];
            }
            unsigned bf[8][2];
            #pragma unroll
            for (int an = 0; an < 8; an++) {
                const int nr = n0 + an * 8;
                bf[an][0] = *(const uint32_t*)&bs[(nr + g) * GP + k0 + 2 * tg];
                bf[an][1] = *(const uint32_t*)&bs[(nr + g) * GP + k0 + 2 * tg + 8];
            }
            #pragma unroll
            for (int am = 0; am < 4; am++)
                #pragma unroll
                for (int an = 0; an < 8; an++)
                    mma_f16(acc[am][an], a[am][0], a[am][1], a[am][2], a[am][3],
                            bf[an][0], bf[an][1]);
        }
        __syncthreads();
        if (it < 6) issue(it & 1, (it + 2) * 32);
    }

    #pragma unroll
    for (int am = 0; am < 4; am++) {
        #pragma unroll
        for (int an = 0; an < 8; an++) {
            const int col = colBase + n0 + an * 8 + 2 * tg;
            const float bi0 = bias[col], bi1 = bias[col + 1];
            #pragma unroll
            for (int half = 0; half < 2; half++) {
                const int row = rowBase + m0 + am * 16 + g + 8 * half;
                float2 v;
                v.x = acc[am][an][2 * half]     + bi0;
                v.y = acc[am][an][2 * half + 1] + bi1;
                if (QKV) {
                    const int b = row >> 6, n = row & 63;
                    const int which = col >> 8;
                    const int h = (col >> 5) & 7;
                    const int d = col & 31;
                    __half* dst = (which == 0) ? g_qh : (which == 1) ? g_kh : g_vh;
                    *(uint32_t*)&dst[((((size_t)b * HEADS + h) * WIN) + n) * HD + d] =
                        pack_f16(v.x, v.y);
                } else {
                    *(float2*)&out[(size_t)row * DIM + col] = v;
                }
            }
        }
    }
}

// ---------------------------------------------------------------------------
// Attention: QK = 3-term bf16, PV = 2-term fp16 (exact: v is fp16 scratch).
// smem: qhi@0 qlo@5120 khi@10240 klo@15360 (bf16, pitch 40)
//       vt@20480 (fp16 transposed, 32 x pitch 72, 4608 B) -> total 25088
//       phi@0, plo@10240 (fp16, pitch 72, alias q/k after QK reads)
// ---------------------------------------------------------------------------
#define QP  40
#define PPB 72
#define VTP 72
#define ATTN_SMEM_BYTES 25088

__global__ void __launch_bounds__(128) attn_kernel(const float* __restrict__ logit_scale)
{
    extern __shared__ char smb[];
    __nv_bfloat16* qhi = (__nv_bfloat16*)(smb);
    __nv_bfloat16* qlo = (__nv_bfloat16*)(smb + 5120);
    __nv_bfloat16* khi = (__nv_bfloat16*)(smb + 10240);
    __nv_bfloat16* klo = (__nv_bfloat16*)(smb + 15360);
    __half*        vt  = (__half*)(smb + 20480);
    __half*        phi = (__half*)(smb);            // alias (after QK)
    __half*        plo = (__half*)(smb + 10240);    // alias (after QK)

    const int bh = blockIdx.x;
    const int b  = bh >> 3;
    const int h  = bh & 7;
    const int tid  = threadIdx.x;
    const int lane = tid & 31;
    const int warp = tid >> 5;
    const int g  = lane >> 2, tg = lane & 3;
    const int m0 = warp * 16;
    const int r0 = m0 + g, r1 = r0 + 8;

    const size_t base = (size_t)bh * WIN * HD;
    const float ls = __expf(fminf(logit_scale[h], 4.6051701859880914f));

    // Phase 0: q/k half-row per thread (norm via shfl), v transpose (fp16 raw)
    {
        const int row = tid >> 1;
        const int d0  = (tid & 1) * 16;
        float qv[16];
        {
            const __half2* qp = (const __half2*)&g_qh[base + row * HD + d0];
            #pragma unroll
            for (int i = 0; i < 8; i++) {
                float2 f = __half22float2(qp[i]);
                qv[2 * i] = f.x; qv[2 * i + 1] = f.y;
            }
        }
        float s = 0.f;
        #pragma unroll
        for (int i = 0; i < 16; i++) s += qv[i] * qv[i];
        s += __shfl_xor_sync(0xffffffffu, s, 1);
        float inv = ls / fmaxf(sqrtf(s), 1e-12f);
        #pragma unroll
        for (int i = 0; i < 16; i += 2) {
            const float x0 = qv[i] * inv, x1 = qv[i + 1] * inv;
            const float h0 = bf16hi(x0), h1 = bf16hi(x1);
            *(uint32_t*)&qhi[row * QP + d0 + i] = pack_bf16(h0, h1);
            *(uint32_t*)&qlo[row * QP + d0 + i] = pack_bf16(x0 - h0, x1 - h1);
        }
        float kv[16];
        {
            const __half2* kp = (const __half2*)&g_kh[base + row * HD + d0];
            #pragma unroll
            for (int i = 0; i < 8; i++) {
                float2 f = __half22float2(kp[i]);
                kv[2 * i] = f.x; kv[2 * i + 1] = f.y;
            }
        }
        s = 0.f;
        #pragma unroll
        for (int i = 0; i < 16; i++) s += kv[i] * kv[i];
        s += __shfl_xor_sync(0xffffffffu, s, 1);
        inv = 1.0f / fmaxf(sqrtf(s), 1e-12f);
        #pragma unroll
        for (int i = 0; i < 16; i += 2) {
            const float x0 = kv[i] * inv, x1 = kv[i + 1] * inv;
            const float h0 = bf16hi(x0), h1 = bf16hi(x1);
            *(uint32_t*)&khi[row * QP + d0 + i] = pack_bf16(h0, h1);
            *(uint32_t*)&klo[row * QP + d0 + i] = pack_bf16(x0 - h0, x1 - h1);
        }
        // v: copy fp16 raw, transposed
        #pragma unroll
        for (int i = 0; i < 4; i++) {
            const int idx = tid + 128 * i;
            const int n = idx >> 3, c = (idx & 7) * 4;
            const __half* vp = &g_vh[base + n * HD + c];
            __half2 v01 = *(const __half2*)(vp);
            __half2 v23 = *(const __half2*)(vp + 2);
            vt[(c + 0) * VTP + n] = __low2half(v01);
            vt[(c + 1) * VTP + n] = __high2half(v01);
            vt[(c + 2) * VTP + n] = __low2half(v23);
            vt[(c + 3) * VTP + n] = __high2half(v23);
        }
    }
    __syncthreads();

    // Prefetch bias+mask (fp16)
    float2 bm0[8], bm1[8];
    {
        const __half* bm = g_bmh + ((size_t)((b & 255) * 8 + h) << 12);
        #pragma unroll
        for (int an = 0; an < 8; an++) {
            const int c = an * 8 + 2 * tg;
            bm0[an] = __half22float2(*(const __half2*)&bm[r0 * 64 + c]);
            bm1[an] = __half22float2(*(const __half2*)&bm[r1 * 64 + c]);
        }
    }

    // QK^T, 3-term bf16
    float acc[8][4] = {};
    #pragma unroll
    for (int kst = 0; kst < 2; kst++) {
        const int kb = kst * 16;
        unsigned ah[4], al[4];
        ah[0] = *(uint32_t*)&qhi[(m0 + g)     * QP + kb + 2 * tg];
        ah[1] = *(uint32_t*)&qhi[(m0 + g + 8) * QP + kb + 2 * tg];
        ah[2] = *(uint32_t*)&qhi[(m0 + g)     * QP + kb + 2 * tg + 8];
        ah[3] = *(uint32_t*)&qhi[(m0 + g + 8) * QP + kb + 2 * tg + 8];
        al[0] = *(uint32_t*)&qlo[(m0 + g)     * QP + kb + 2 * tg];
        al[1] = *(uint32_t*)&qlo[(m0 + g + 8) * QP + kb + 2 * tg];
        al[2] = *(uint32_t*)&qlo[(m0 + g)     * QP + kb + 2 * tg + 8];
        al[3] = *(uint32_t*)&qlo[(m0 + g + 8) * QP + kb + 2 * tg + 8];
        #pragma unroll
        for (int an = 0; an < 8; an++) {
            const int nr = an * 8;
            unsigned bh0 = *(uint32_t*)&khi[(nr + g) * QP + kb + 2 * tg];
            unsigned bh1 = *(uint32_t*)&khi[(nr + g) * QP + kb + 2 * tg + 8];
            unsigned bl0 = *(uint32_t*)&klo[(nr + g) * QP + kb + 2 * tg];
            unsigned bl1 = *(uint32_t*)&klo[(nr + g) * QP + kb + 2 * tg + 8];
            mma_bf16(acc[an], ah[0], ah[1], ah[2], ah[3], bh0, bh1);
            mma_bf16(acc[an], ah[0], ah[1], ah[2], ah[3], bl0, bl1);
            mma_bf16(acc[an], al[0], al[1], al[2], al[3], bh0, bh1);
        }
    }
    __syncthreads();   // QK smem reads done before P writes alias q/k

    // bias+mask add + register softmax; write P hi/lo fp16
    {
        float m0v = -1e30f, m1v = -1e30f;
        #pragma unroll
        for (int an = 0; an < 8; an++) {
            acc[an][0] += bm0[an].x; acc[an][1] += bm0[an].y;
            acc[an][2] += bm1[an].x; acc[an][3] += bm1[an].y;
            m0v = fmaxf(m0v, fmaxf(acc[an][0], acc[an][1]));
            m1v = fmaxf(m1v, fmaxf(acc[an][2], acc[an][3]));
        }
        m0v = fmaxf(m0v, __shfl_xor_sync(0xffffffffu, m0v, 1));
        m0v = fmaxf(m0v, __shfl_xor_sync(0xffffffffu, m0v, 2));
        m1v = fmaxf(m1v, __shfl_xor_sync(0xffffffffu, m1v, 1));
        m1v = fmaxf(m1v, __shfl_xor_sync(0xffffffffu, m1v, 2));
        float s0 = 0.f, s1 = 0.f;
        #pragma unroll
        for (int an = 0; an < 8; an++) {
            acc[an][0] = __expf(acc[an][0] - m0v); s0 += acc[an][0];
            acc[an][1] = __expf(acc[an][1] - m0v); s0 += acc[an][1];
            acc[an][2] = __expf(acc[an][2] - m1v); s1 += acc[an][2];
            acc[an][3] = __expf(acc[an][3] - m1v); s1 += acc[an][3];
        }
        s0 += __shfl_xor_sync(0xffffffffu, s0, 1);
        s0 += __shfl_xor_sync(0xffffffffu, s0, 2);
        s1 += __shfl_xor_sync(0xffffffffu, s1, 1);
        s1 += __shfl_xor_sync(0xffffffffu, s1, 2);
        const float i0 = 1.0f / s0, i1 = 1.0f / s1;
        #pragma unroll
        for (int an = 0; an < 8; an++) {
            const int c = an * 8 + 2 * tg;
            const float p00 = acc[an][0] * i0, p01 = acc[an][1] * i0;
            const float p10 = acc[an][2] * i1, p11 = acc[an][3] * i1;
            const float h00 = f16hi(p00), h01 = f16hi(p01);
            const float h10 = f16hi(p10), h11 = f16hi(p11);
            *(uint32_t*)&phi[r0 * PPB + c] = pack_f16(h00, h01);
            *(uint32_t*)&phi[r1 * PPB + c] = pack_f16(h10, h11);
            *(uint32_t*)&plo[r0 * PPB + c] = pack_f16(p00 - h00, p01 - h01);
            *(uint32_t*)&plo[r1 * PPB + c] = pack_f16(p10 - h10, p11 - h11);
        }
    }
    __syncwarp();

    // P @ V: 2-term fp16 (exact — v single fp16 operand)
    float oacc[4][4] = {};
    #pragma unroll
    for (int kst = 0; kst < 4; kst++) {
        const int kb = kst * 16;
        unsigned ah[4], al[4];
        ah[0] = *(uint32_t*)&phi[(m0 + g)     * PPB + kb + 2 * tg];
        ah[1] = *(uint32_t*)&phi[(m0 + g + 8) * PPB + kb + 2 * tg];
        ah[2] = *(uint32_t*)&phi[(m0 + g)     * PPB + kb + 2 * tg + 8];
        ah[3] = *(uint32_t*)&phi[(m0 + g + 8) * PPB + kb + 2 * tg + 8];
        al[0] = *(uint32_t*)&plo[(m0 + g)     * PPB + kb + 2 * tg];
        al[1] = *(uint32_t*)&plo[(m0 + g + 8) * PPB + kb + 2 * tg];
        al[2] = *(uint32_t*)&plo[(m0 + g)     * PPB + kb + 2 * tg + 8];
        al[3] = *(uint32_t*)&plo[(m0 + g + 8) * PPB + kb + 2 * tg + 8];
        #pragma unroll
        for (int dn = 0; dn < 4; dn++) {
            const int nn = dn * 8;
            unsigned b0 = *(uint32_t*)&vt[(nn + g) * VTP + kb + 2 * tg];
            unsigned b1 = *(uint32_t*)&vt[(nn + g) * VTP + kb + 2 * tg + 8];
            mma_f16(oacc[dn], ah[0], ah[1], ah[2], ah[3], b0, b1);
            mma_f16(oacc[dn], al[0], al[1], al[2], al[3], b0, b1);
        }
    }

    __half* aop = g_aoh + (size_t)b * WIN * DIM + h * HD;
    #pragma unroll
    for (int dn = 0; dn < 4; dn++) {
        const int c = dn * 8 + 2 * tg;
        *(uint32_t*)&aop[(size_t)r0 * DIM + c] = pack_f16(oacc[dn][0], oacc[dn][1]);
        *(uint32_t*)&aop[(size_t)r1 * DIM + c] = pack_f16(oacc[dn][2], oacc[dn][3]);
    }
}

// ---------------------------------------------------------------------------
extern "C" void kernel_launch(void* const* d_in, const int* in_sizes, int n_in,
                              void* d_out, int out_size)
{
    const float* x        = (const float*)d_in[0];
    const float* mask     = (const float*)d_in[1];
    const float* qkv_w    = (const float*)d_in[2];
    const float* qkv_b    = (const float*)d_in[3];
    const float* proj_w   = (const float*)d_in[4];
    const float* proj_b   = (const float*)d_in[5];
    const float* lscale   = (const float*)d_in[6];
    const float* btable   = (const float*)d_in[7];
    const int*   rpi      = (const int*)d_in[8];
    float* out = (float*)d_out;

    cudaFuncSetAttribute(attn_kernel, cudaFuncAttributeMaxDynamicSharedMemorySize,
                         ATTN_SMEM_BYTES);

    __half *xh, *wqh, *wph, *aoh;
    cudaGetSymbolAddress((void**)&xh,  g_xh);
    cudaGetSymbolAddress((void**)&wqh, g_wqh);
    cudaGetSymbolAddress((void**)&wph, g_wph);
    cudaGetSymbolAddress((void**)&aoh, g_aoh);

    // 0) pre-passes
    conv_f16<<<(MROWS*DIM/4 + 255)/256, 256>>>(x, xh, MROWS*DIM/4);
    conv_f16<<<(QKV_N*DIM/4 + 255)/256, 256>>>(qkv_w, wqh, QKV_N*DIM/4);
    conv_f16<<<(DIM*DIM/4 + 255)/256, 256>>>(proj_w, wph, DIM*DIM/4);
    bm_pre<<<8192, 256>>>(btable, rpi, mask);

    // 1) QKV projection
    {
        dim3 grid(QKV_N / 128, MROWS / 128);
        mma_gemm<true><<<grid, 128>>>(xh, wqh, qkv_b, nullptr);
    }
    // 2) Attention per (window, head)
    {
        attn_kernel<<<NWIN * HEADS, 128, ATTN_SMEM_BYTES>>>(lscale);
    }
    // 3) Output projection
    {
        dim3 grid(DIM / 128, MROWS / 128);
        mma_gemm<false><<<grid, 128>>>(aoh, wph, proj_b, out);
    }
}

// round 15
// speedup vs baseline: 1.8347x; 1.0084x over previous
#include <cuda_runtime.h>
#include <cuda_bf16.h>
#include <cuda_fp16.h>
#include <cstdint>

#define NWIN   2048
#define WIN    64
#define DIM    256
#define HEADS  8
#define HD     32
#define QKV_N  768
#define MROWS  (NWIN*WIN)  // 131072

__device__ __half g_qh[(size_t)NWIN*HEADS*WIN*HD];
__device__ __half g_kh[(size_t)NWIN*HEADS*WIN*HD];
__device__ __half g_vh[(size_t)NWIN*HEADS*WIN*HD];
__device__ __half g_bmh[(size_t)256*HEADS*WIN*WIN];
__device__ __half g_xh[(size_t)MROWS*DIM];
__device__ __half g_aoh[(size_t)MROWS*DIM];
__device__ __half g_wqh[QKV_N*DIM];
__device__ __half g_wph[DIM*DIM];

__device__ __forceinline__ uint32_t pack_f16(float a, float b) {
    __half2 t = __floats2half2_rn(a, b);
    return *(uint32_t*)&t;
}
__device__ __forceinline__ float f16hi(float x) {
    return __half2float(__float2half_rn(x));
}

__device__ __forceinline__ void mma_f16(float c[4],
                                        unsigned a0, unsigned a1, unsigned a2, unsigned a3,
                                        unsigned b0, unsigned b1) {
    asm volatile(
        "mma.sync.aligned.m16n8k16.row.col.f32.f16.f16.f32 "
        "{%0,%1,%2,%3}, {%4,%5,%6,%7}, {%8,%9}, {%0,%1,%2,%3};"
        : "+f"(c[0]), "+f"(c[1]), "+f"(c[2]), "+f"(c[3])
        : "r"(a0), "r"(a1), "r"(a2), "r"(a3), "r"(b0), "r"(b1));
}

__device__ __forceinline__ void cp16(uint32_t dst, const void* src) {
    asm volatile("cp.async.cg.shared.global [%0], [%1], 16;" :: "r"(dst), "l"(src));
}

// ---------------------------------------------------------------------------
// fp32 -> fp16 conversion pre-pass
// ---------------------------------------------------------------------------
__global__ void conv_f16(const float* __restrict__ src, __half* __restrict__ dst, int n4)
{
    const int i = blockIdx.x * 256 + threadIdx.x;
    if (i < n4) {
        float4 v = ((const float4*)src)[i];
        ((uint2*)dst)[i] = make_uint2(pack_f16(v.x, v.y), pack_f16(v.z, v.w));
    }
}

// ---------------------------------------------------------------------------
// bias+mask tables (fp16): bias table staged in smem, 4 elems/thread
// ---------------------------------------------------------------------------
__global__ void bm_pre(const float* __restrict__ bt, const int* __restrict__ rpi,
                       const float* __restrict__ mask)
{
    __shared__ float sbt[225 * 8];
    for (int i = threadIdx.x; i < 225 * 8; i += 256) sbt[i] = bt[i];
    __syncthreads();

    const int i4 = blockIdx.x * 256 + threadIdx.x;   // 0..2097151
    const int e = (i4 & 1023) * 4;
    const int h = (i4 >> 10) & 7;
    const int w = i4 >> 13;
    float4 m = *(const float4*)&mask[w * 4096 + e];
    const float b0 = sbt[rpi[e]     * HEADS + h];
    const float b1 = sbt[rpi[e + 1] * HEADS + h];
    const float b2 = sbt[rpi[e + 2] * HEADS + h];
    const float b3 = sbt[rpi[e + 3] * HEADS + h];
    *(uint2*)&g_bmh[(((size_t)(w * 8 + h)) << 12) + e] =
        make_uint2(pack_f16(b0 + m.x, b1 + m.y), pack_f16(b2 + m.z, b3 + m.w));
}

// ---------------------------------------------------------------------------
// GEMM (round-12 proven): fp16 cp.async 2-stage, block 128x128, warp 64x64.
// ---------------------------------------------------------------------------
#define GP 40

template<bool QKV>
__global__ void __launch_bounds__(128, 2) mma_gemm(const __half* __restrict__ A,
                                                   const __half* __restrict__ W,
                                                   const float* __restrict__ bias,
                                                   float* __restrict__ out)
{
    const int K = DIM;
    __shared__ __half As[2][128 * GP];
    __shared__ __half Bs[2][128 * GP];
    uint32_t sA[2], sB[2];
    #pragma unroll
    for (int s = 0; s < 2; s++) {
        sA[s] = (uint32_t)__cvta_generic_to_shared(&As[s][0]);
        sB[s] = (uint32_t)__cvta_generic_to_shared(&Bs[s][0]);
    }

    const int rowBase = blockIdx.y * 128;
    const int colBase = blockIdx.x * 128;
    const int tid  = threadIdx.x;
    const int lane = tid & 31;
    const int warp = tid >> 5;
    const int warpM = warp >> 1;
    const int warpN = warp & 1;
    const int g  = lane >> 2;
    const int tg = lane & 3;
    const int m0 = warpM * 64;
    const int n0 = warpN * 64;

    const int lr = tid >> 2;
    const int lc8 = (tid & 3) * 8;

    auto issue = [&](int buf, int kb) {
        #pragma unroll
        for (int i = 0; i < 4; i++) {
            const int r = lr + 32 * i;
            const uint32_t off = (uint32_t)(r * GP + lc8) * 2;
            cp16(sA[buf] + off, &A[(size_t)(rowBase + r) * K + kb + lc8]);
            cp16(sB[buf] + off, &W[(size_t)(colBase + r) * K + kb + lc8]);
        }
        asm volatile("cp.async.commit_group;");
    };

    issue(0, 0);
    issue(1, 32);

    float acc[4][8][4] = {};

    for (int it = 0; it < 8; it++) {
        if (it == 7) asm volatile("cp.async.wait_group 0;");
        else         asm volatile("cp.async.wait_group 1;");
        __syncthreads();
        const __half* as = As[it & 1];
        const __half* bs = Bs[it & 1];

        #pragma unroll
        for (int ks = 0; ks < 2; ks++) {
            const int k0 = ks * 16;
            unsigned a[4][4];
            #pragma unroll
            for (int am = 0; am < 4; am++) {
                const int mr = m0 + am * 16;
                a[am][0] = *(const uint32_t*)&as[(mr + g)     * GP + k0 + 2 * tg];
                a[am][1] = *(const uint32_t*)&as[(mr + g + 8) * GP + k0 + 2 * tg];
                a[am][2] = *(const uint32_t*)&as[(mr + g)     * GP + k0 + 2 * tg + 8];
                a[am][3] = *(const uint32_t*)&as[(mr + g + 8) * GP + k0 + 2 * tg + 8];
            }
            unsigned bf[8][2];
            #pragma unroll
            for (int an = 0; an < 8; an++) {
                const int nr = n0 + an * 8;
                bf[an][0] = *(const uint32_t*)&bs[(nr + g) * GP + k0 + 2 * tg];
                bf[an][1] = *(const uint32_t*)&bs[(nr + g) * GP + k0 + 2 * tg + 8];
            }
            #pragma unroll
            for (int am = 0; am < 4; am++)
                #pragma unroll
                for (int an = 0; an < 8; an++)
                    mma_f16(acc[am][an], a[am][0], a[am][1], a[am][2], a[am][3],
                            bf[an][0], bf[an][1]);
        }
        __syncthreads();
        if (it < 6) issue(it & 1, (it + 2) * 32);
    }

    #pragma unroll
    for (int am = 0; am < 4; am++) {
        #pragma unroll
        for (int an = 0; an < 8; an++) {
            const int col = colBase + n0 + an * 8 + 2 * tg;
            const float bi0 = bias[col], bi1 = bias[col + 1];
            #pragma unroll
            for (int half = 0; half < 2; half++) {
                const int row = rowBase + m0 + am * 16 + g + 8 * half;
                float2 v;
                v.x = acc[am][an][2 * half]     + bi0;
                v.y = acc[am][an][2 * half + 1] + bi1;
                if (QKV) {
                    const int b = row >> 6, n = row & 63;
                    const int which = col >> 8;
                    const int h = (col >> 5) & 7;
                    const int d = col & 31;
                    __half* dst = (which == 0) ? g_qh : (which == 1) ? g_kh : g_vh;
                    *(uint32_t*)&dst[((((size_t)b * HEADS + h) * WIN) + n) * HD + d] =
                        pack_f16(v.x, v.y);
                } else {
                    *(float2*)&out[(size_t)row * DIM + col] = v;
                }
            }
        }
    }
}

// ---------------------------------------------------------------------------
// Attention v4: normalization commuted out of the MMA.
//   S = q·k^T with plain fp16 MMA (inputs exact, fp32 accum -> near-exact),
//   logits = S * (ls/|q|) * (1/|k|) + bm;  softmax;  PV = 2-term fp16 (exact).
// smem (bytes):
//   qs@0 (64x40 fp16, 5120), ks@5120 (5120)        [raw fp16 q/k]
//   phi@0 (9216), plo@9216 (9216)                  [alias after QK reads]
//   vt@18432 (32x72 fp16, 4608)
//   invq@23040 (64 f32), invk@23296 (64 f32)       -> total 23552
// ---------------------------------------------------------------------------
#define QP  40
#define PPB 72
#define VTP 72
#define ATTN_SMEM_BYTES 23552

__global__ void __launch_bounds__(128) attn_kernel(const float* __restrict__ logit_scale)
{
    extern __shared__ char smb[];
    __half* qs  = (__half*)(smb);
    __half* ks  = (__half*)(smb + 5120);
    __half* phi = (__half*)(smb);            // alias (after QK)
    __half* plo = (__half*)(smb + 9216);     // alias (after QK)
    __half* vt  = (__half*)(smb + 18432);
    float* invq = (float*)(smb + 23040);
    float* invk = (float*)(smb + 23296);

    const int bh = blockIdx.x;
    const int b  = bh >> 3;
    const int h  = bh & 7;
    const int tid  = threadIdx.x;
    const int lane = tid & 31;
    const int warp = tid >> 5;
    const int g  = lane >> 2, tg = lane & 3;
    const int m0 = warp * 16;
    const int r0 = m0 + g, r1 = r0 + 8;

    const size_t base = (size_t)bh * WIN * HD;
    const float ls = __expf(fminf(logit_scale[h], 4.6051701859880914f));

    // Phase 0: raw fp16 q/k copy + norms; v transpose
    {
        const int row = tid >> 1;
        const int d0  = (tid & 1) * 16;
        // q
        {
            uint32_t raw[8];
            const uint32_t* qp = (const uint32_t*)&g_qh[base + row * HD + d0];
            float s = 0.f;
            #pragma unroll
            for (int i = 0; i < 8; i++) {
                raw[i] = qp[i];
                float2 f = __half22float2(*(__half2*)&raw[i]);
                s += f.x * f.x + f.y * f.y;
            }
            s += __shfl_xor_sync(0xffffffffu, s, 1);
            if ((tid & 1) == 0) invq[row] = ls / fmaxf(sqrtf(s), 1e-12f);
            #pragma unroll
            for (int i = 0; i < 8; i++)
                *(uint32_t*)&qs[row * QP + d0 + 2 * i] = raw[i];
        }
        // k
        {
            uint32_t raw[8];
            const uint32_t* kp = (const uint32_t*)&g_kh[base + row * HD + d0];
            float s = 0.f;
            #pragma unroll
            for (int i = 0; i < 8; i++) {
                raw[i] = kp[i];
                float2 f = __half22float2(*(__half2*)&raw[i]);
                s += f.x * f.x + f.y * f.y;
            }
            s += __shfl_xor_sync(0xffffffffu, s, 1);
            if ((tid & 1) == 0) invk[row] = 1.0f / fmaxf(sqrtf(s), 1e-12f);
            #pragma unroll
            for (int i = 0; i < 8; i++)
                *(uint32_t*)&ks[row * QP + d0 + 2 * i] = raw[i];
        }
        // v transpose (raw fp16)
        #pragma unroll
        for (int i = 0; i < 4; i++) {
            const int idx = tid + 128 * i;
            const int n = idx >> 3, c = (idx & 7) * 4;
            const __half* vp = &g_vh[base + n * HD + c];
            __half2 v01 = *(const __half2*)(vp);
            __half2 v23 = *(const __half2*)(vp + 2);
            vt[(c + 0) * VTP + n] = __low2half(v01);
            vt[(c + 1) * VTP + n] = __high2half(v01);
            vt[(c + 2) * VTP + n] = __low2half(v23);
            vt[(c + 3) * VTP + n] = __high2half(v23);
        }
    }
    __syncthreads();

    // Prefetch bias+mask (fp16)
    float2 bm0[8], bm1[8];
    {
        const __half* bm = g_bmh + ((size_t)((b & 255) * 8 + h) << 12);
        #pragma unroll
        for (int an = 0; an < 8; an++) {
            const int c = an * 8 + 2 * tg;
            bm0[an] = __half22float2(*(const __half2*)&bm[r0 * 64 + c]);
            bm1[an] = __half22float2(*(const __half2*)&bm[r1 * 64 + c]);
        }
    }

    // QK^T: single plain fp16 MMA pass (exact)
    float acc[8][4] = {};
    #pragma unroll
    for (int kst = 0; kst < 2; kst++) {
        const int kb = kst * 16;
        unsigned a0 = *(uint32_t*)&qs[(m0 + g)     * QP + kb + 2 * tg];
        unsigned a1 = *(uint32_t*)&qs[(m0 + g + 8) * QP + kb + 2 * tg];
        unsigned a2 = *(uint32_t*)&qs[(m0 + g)     * QP + kb + 2 * tg + 8];
        unsigned a3 = *(uint32_t*)&qs[(m0 + g + 8) * QP + kb + 2 * tg + 8];
        #pragma unroll
        for (int an = 0; an < 8; an++) {
            const int nr = an * 8;
            unsigned b0 = *(uint32_t*)&ks[(nr + g) * QP + kb + 2 * tg];
            unsigned b1 = *(uint32_t*)&ks[(nr + g) * QP + kb + 2 * tg + 8];
            mma_f16(acc[an], a0, a1, a2, a3, b0, b1);
        }
    }

    // Scale by norms + bias/mask
    const float iq0 = invq[r0], iq1 = invq[r1];
    #pragma unroll
    for (int an = 0; an < 8; an++) {
        const int c = an * 8 + 2 * tg;
        const float ik0 = invk[c], ik1 = invk[c + 1];
        acc[an][0] = acc[an][0] * iq0 * ik0 + bm0[an].x;
        acc[an][1] = acc[an][1] * iq0 * ik1 + bm0[an].y;
        acc[an][2] = acc[an][2] * iq1 * ik0 + bm1[an].x;
        acc[an][3] = acc[an][3] * iq1 * ik1 + bm1[an].y;
    }
    __syncthreads();   // all QK smem reads done before P writes alias q/k

    // Register softmax; write P hi/lo fp16
    {
        float m0v = -1e30f, m1v = -1e30f;
        #pragma unroll
        for (int an = 0; an < 8; an++) {
            m0v = fmaxf(m0v, fmaxf(acc[an][0], acc[an][1]));
            m1v = fmaxf(m1v, fmaxf(acc[an][2], acc[an][3]));
        }
        m0v = fmaxf(m0v, __shfl_xor_sync(0xffffffffu, m0v, 1));
        m0v = fmaxf(m0v, __shfl_xor_sync(0xffffffffu, m0v, 2));
        m1v = fmaxf(m1v, __shfl_xor_sync(0xffffffffu, m1v, 1));
        m1v = fmaxf(m1v, __shfl_xor_sync(0xffffffffu, m1v, 2));
        float s0 = 0.f, s1 = 0.f;
        #pragma unroll
        for (int an = 0; an < 8; an++) {
            acc[an][0] = __expf(acc[an][0] - m0v); s0 += acc[an][0];
            acc[an][1] = __expf(acc[an][1] - m0v); s0 += acc[an][1];
            acc[an][2] = __expf(acc[an][2] - m1v); s1 += acc[an][2];
            acc[an][3] = __expf(acc[an][3] - m1v); s1 += acc[an][3];
        }
        s0 += __shfl_xor_sync(0xffffffffu, s0, 1);
        s0 += __shfl_xor_sync(0xffffffffu, s0, 2);
        s1 += __shfl_xor_sync(0xffffffffu, s1, 1);
        s1 += __shfl_xor_sync(0xffffffffu, s1, 2);
        const float i0 = 1.0f / s0, i1 = 1.0f / s1;
        #pragma unroll
        for (int an = 0; an < 8; an++) {
            const int c = an * 8 + 2 * tg;
            const float p00 = acc[an][0] * i0, p01 = acc[an][1] * i0;
            const float p10 = acc[an][2] * i1, p11 = acc[an][3] * i1;
            const float h00 = f16hi(p00), h01 = f16hi(p01);
            const float h10 = f16hi(p10), h11 = f16hi(p11);
            *(uint32_t*)&phi[r0 * PPB + c] = pack_f16(h00, h01);
            *(uint32_t*)&phi[r1 * PPB + c] = pack_f16(h10, h11);
            *(uint32_t*)&plo[r0 * PPB + c] = pack_f16(p00 - h00, p01 - h01);
            *(uint32_t*)&plo[r1 * PPB + c] = pack_f16(p10 - h10, p11 - h11);
        }
    }
    __syncwarp();   // warp reads only its own 16 P-rows

    // P @ V: 2-term fp16 (exact)
    float oacc[4][4] = {};
    #pragma unroll
    for (int kst = 0; kst < 4; kst++) {
        const int kb = kst * 16;
        unsigned ah[4], al[4];
        ah[0] = *(uint32_t*)&phi[(m0 + g)     * PPB + kb + 2 * tg];
        ah[1] = *(uint32_t*)&phi[(m0 + g + 8) * PPB + kb + 2 * tg];
        ah[2] = *(uint32_t*)&phi[(m0 + g)     * PPB + kb + 2 * tg + 8];
        ah[3] = *(uint32_t*)&phi[(m0 + g + 8) * PPB + kb + 2 * tg + 8];
        al[0] = *(uint32_t*)&plo[(m0 + g)     * PPB + kb + 2 * tg];
        al[1] = *(uint32_t*)&plo[(m0 + g + 8) * PPB + kb + 2 * tg];
        al[2] = *(uint32_t*)&plo[(m0 + g)     * PPB + kb + 2 * tg + 8];
        al[3] = *(uint32_t*)&plo[(m0 + g + 8) * PPB + kb + 2 * tg + 8];
        #pragma unroll
        for (int dn = 0; dn < 4; dn++) {
            const int nn = dn * 8;
            unsigned b0 = *(uint32_t*)&vt[(nn + g) * VTP + kb + 2 * tg];
            unsigned b1 = *(uint32_t*)&vt[(nn + g) * VTP + kb + 2 * tg + 8];
            mma_f16(oacc[dn], ah[0], ah[1], ah[2], ah[3], b0, b1);
            mma_f16(oacc[dn], al[0], al[1], al[2], al[3], b0, b1);
        }
    }

    __half* aop = g_aoh + (size_t)b * WIN * DIM + h * HD;
    #pragma unroll
    for (int dn = 0; dn < 4; dn++) {
        const int c = dn * 8 + 2 * tg;
        *(uint32_t*)&aop[(size_t)r0 * DIM + c] = pack_f16(oacc[dn][0], oacc[dn][1]);
        *(uint32_t*)&aop[(size_t)r1 * DIM + c] = pack_f16(oacc[dn][2], oacc[dn][3]);
    }
}

// ---------------------------------------------------------------------------
extern "C" void kernel_launch(void* const* d_in, const int* in_sizes, int n_in,
                              void* d_out, int out_size)
{
    const float* x        = (const float*)d_in[0];
    const float* mask     = (const float*)d_in[1];
    const float* qkv_w    = (const float*)d_in[2];
    const float* qkv_b    = (const float*)d_in[3];
    const float* proj_w   = (const float*)d_in[4];
    const float* proj_b   = (const float*)d_in[5];
    const float* lscale   = (const float*)d_in[6];
    const float* btable   = (const float*)d_in[7];
    const int*   rpi      = (const int*)d_in[8];
    float* out = (float*)d_out;

    cudaFuncSetAttribute(attn_kernel, cudaFuncAttributeMaxDynamicSharedMemorySize,
                         ATTN_SMEM_BYTES);

    __half *xh, *wqh, *wph, *aoh;
    cudaGetSymbolAddress((void**)&xh,  g_xh);
    cudaGetSymbolAddress((void**)&wqh, g_wqh);
    cudaGetSymbolAddress((void**)&wph, g_wph);
    cudaGetSymbolAddress((void**)&aoh, g_aoh);

    // 0) pre-passes
    conv_f16<<<(MROWS*DIM/4 + 255)/256, 256>>>(x, xh, MROWS*DIM/4);
    conv_f16<<<(QKV_N*DIM/4 + 255)/256, 256>>>(qkv_w, wqh, QKV_N*DIM/4);
    conv_f16<<<(DIM*DIM/4 + 255)/256, 256>>>(proj_w, wph, DIM*DIM/4);
    bm_pre<<<8192, 256>>>(btable, rpi, mask);

    // 1) QKV projection
    {
        dim3 grid(QKV_N / 128, MROWS / 128);
        mma_gemm<true><<<grid, 128>>>(xh, wqh, qkv_b, nullptr);
    }
    // 2) Attention per (window, head)
    {
        attn_kernel<<<NWIN * HEADS, 128, ATTN_SMEM_BYTES>>>(lscale);
    }
    // 3) Output projection
    {
        dim3 grid(DIM / 128, MROWS / 128);
        mma_gemm<false><<<grid, 128>>>(aoh, wph, proj_b, out);
    }
}

// round 16
// speedup vs baseline: 1.8945x; 1.0326x over previous
#include <cuda_runtime.h>
#include <cuda_bf16.h>
#include <cuda_fp16.h>
#include <cstdint>

#define NWIN   2048
#define WIN    64
#define DIM    256
#define HEADS  8
#define HD     32
#define QKV_N  768
#define MROWS  (NWIN*WIN)  // 131072

__device__ __half g_qh[(size_t)NWIN*HEADS*WIN*HD];
__device__ __half g_kh[(size_t)NWIN*HEADS*WIN*HD];
__device__ __half g_vh[(size_t)NWIN*HEADS*WIN*HD];
__device__ __half g_bmh[(size_t)256*HEADS*WIN*WIN];
__device__ __half g_xh[(size_t)MROWS*DIM];
__device__ __half g_aoh[(size_t)MROWS*DIM];
__device__ __half g_wqh[QKV_N*DIM];
__device__ __half g_wph[DIM*DIM];

__device__ __forceinline__ uint32_t pack_f16(float a, float b) {
    __half2 t = __floats2half2_rn(a, b);
    return *(uint32_t*)&t;
}

__device__ __forceinline__ void mma_f16(float c[4],
                                        unsigned a0, unsigned a1, unsigned a2, unsigned a3,
                                        unsigned b0, unsigned b1) {
    asm volatile(
        "mma.sync.aligned.m16n8k16.row.col.f32.f16.f16.f32 "
        "{%0,%1,%2,%3}, {%4,%5,%6,%7}, {%8,%9}, {%0,%1,%2,%3};"
        : "+f"(c[0]), "+f"(c[1]), "+f"(c[2]), "+f"(c[3])
        : "r"(a0), "r"(a1), "r"(a2), "r"(a3), "r"(b0), "r"(b1));
}

__device__ __forceinline__ void cp16(uint32_t dst, const void* src) {
    asm volatile("cp.async.cg.shared.global [%0], [%1], 16;" :: "r"(dst), "l"(src));
}

// ---------------------------------------------------------------------------
// fp32 -> fp16 conversion pre-pass
// ---------------------------------------------------------------------------
__global__ void conv_f16(const float* __restrict__ src, __half* __restrict__ dst, int n4)
{
    const int i = blockIdx.x * 256 + threadIdx.x;
    if (i < n4) {
        float4 v = ((const float4*)src)[i];
        ((uint2*)dst)[i] = make_uint2(pack_f16(v.x, v.y), pack_f16(v.z, v.w));
    }
}

// ---------------------------------------------------------------------------
// bias+mask tables (fp16), 4 elements per thread (round-14 proven)
// ---------------------------------------------------------------------------
__global__ void bm_pre(const float* __restrict__ bt, const int* __restrict__ rpi,
                       const float* __restrict__ mask)
{
    const int i4 = blockIdx.x * 256 + threadIdx.x;   // 0..2097151
    const int e = (i4 & 1023) * 4;
    const int h = (i4 >> 10) & 7;
    const int w = i4 >> 13;
    float4 m = *(const float4*)&mask[w * 4096 + e];
    const float b0 = bt[rpi[e]     * HEADS + h];
    const float b1 = bt[rpi[e + 1] * HEADS + h];
    const float b2 = bt[rpi[e + 2] * HEADS + h];
    const float b3 = bt[rpi[e + 3] * HEADS + h];
    *(uint2*)&g_bmh[(((size_t)(w * 8 + h)) << 12) + e] =
        make_uint2(pack_f16(b0 + m.x, b1 + m.y), pack_f16(b2 + m.z, b3 + m.w));
}

// ---------------------------------------------------------------------------
// GEMM (round-12 proven): fp16 cp.async 2-stage, block 128x128, warp 64x64.
// ---------------------------------------------------------------------------
#define GP 40

template<bool QKV>
__global__ void __launch_bounds__(128, 2) mma_gemm(const __half* __restrict__ A,
                                                   const __half* __restrict__ W,
                                                   const float* __restrict__ bias,
                                                   float* __restrict__ out)
{
    const int K = DIM;
    __shared__ __half As[2][128 * GP];
    __shared__ __half Bs[2][128 * GP];
    uint32_t sA[2], sB[2];
    #pragma unroll
    for (int s = 0; s < 2; s++) {
        sA[s] = (uint32_t)__cvta_generic_to_shared(&As[s][0]);
        sB[s] = (uint32_t)__cvta_generic_to_shared(&Bs[s][0]);
    }

    const int rowBase = blockIdx.y * 128;
    const int colBase = blockIdx.x * 128;
    const int tid  = threadIdx.x;
    const int lane = tid & 31;
    const int warp = tid >> 5;
    const int warpM = warp >> 1;
    const int warpN = warp & 1;
    const int g  = lane >> 2;
    const int tg = lane & 3;
    const int m0 = warpM * 64;
    const int n0 = warpN * 64;

    const int lr = tid >> 2;
    const int lc8 = (tid & 3) * 8;

    auto issue = [&](int buf, int kb) {
        #pragma unroll
        for (int i = 0; i < 4; i++) {
            const int r = lr + 32 * i;
            const uint32_t off = (uint32_t)(r * GP + lc8) * 2;
            cp16(sA[buf] + off, &A[(size_t)(rowBase + r) * K + kb + lc8]);
            cp16(sB[buf] + off, &W[(size_t)(colBase + r) * K + kb + lc8]);
        }
        asm volatile("cp.async.commit_group;");
    };

    issue(0, 0);
    issue(1, 32);

    float acc[4][8][4] = {};

    for (int it = 0; it < 8; it++) {
        if (it == 7) asm volatile("cp.async.wait_group 0;");
        else         asm volatile("cp.async.wait_group 1;");
        __syncthreads();
        const __half* as = As[it & 1];
        const __half* bs = Bs[it & 1];

        #pragma unroll
        for (int ks = 0; ks < 2; ks++) {
            const int k0 = ks * 16;
            unsigned a[4][4];
            #pragma unroll
            for (int am = 0; am < 4; am++) {
                const int mr = m0 + am * 16;
                a[am][0] = *(const uint32_t*)&as[(mr + g)     * GP + k0 + 2 * tg];
                a[am][1] = *(const uint32_t*)&as[(mr + g + 8) * GP + k0 + 2 * tg];
                a[am][2] = *(const uint32_t*)&as[(mr + g)     * GP + k0 + 2 * tg + 8];
                a[am][3] = *(const uint32_t*)&as[(mr + g + 8) * GP + k0 + 2 * tg + 8];
            }
            unsigned bf[8][2];
            #pragma unroll
            for (int an = 0; an < 8; an++) {
                const int nr = n0 + an * 8;
                bf[an][0] = *(const uint32_t*)&bs[(nr + g) * GP + k0 + 2 * tg];
                bf[an][1] = *(const uint32_t*)&bs[(nr + g) * GP + k0 + 2 * tg + 8];
            }
            #pragma unroll
            for (int am = 0; am < 4; am++)
                #pragma unroll
                for (int an = 0; an < 8; an++)
                    mma_f16(acc[am][an], a[am][0], a[am][1], a[am][2], a[am][3],
                            bf[an][0], bf[an][1]);
        }
        __syncthreads();
        if (it < 6) issue(it & 1, (it + 2) * 32);
    }

    #pragma unroll
    for (int am = 0; am < 4; am++) {
        #pragma unroll
        for (int an = 0; an < 8; an++) {
            const int col = colBase + n0 + an * 8 + 2 * tg;
            const float bi0 = bias[col], bi1 = bias[col + 1];
            #pragma unroll
            for (int half = 0; half < 2; half++) {
                const int row = rowBase + m0 + am * 16 + g + 8 * half;
                float2 v;
                v.x = acc[am][an][2 * half]     + bi0;
                v.y = acc[am][an][2 * half + 1] + bi1;
                if (QKV) {
                    const int b = row >> 6, n = row & 63;
                    const int which = col >> 8;
                    const int h = (col >> 5) & 7;
                    const int d = col & 31;
                    __half* dst = (which == 0) ? g_qh : (which == 1) ? g_kh : g_vh;
                    *(uint32_t*)&dst[((((size_t)b * HEADS + h) * WIN) + n) * HD + d] =
                        pack_f16(v.x, v.y);
                } else {
                    *(float2*)&out[(size_t)row * DIM + col] = v;
                }
            }
        }
    }
}

// ---------------------------------------------------------------------------
// Attention v5: QK plain fp16 (exact, norms commuted out), PV single fp16.
// smem: qs@0 (5120), ks@5120 (5120)   [raw fp16, pitch 40]
//       p@0 (9216 via pitch 72)       [alias after QK reads]
//       vt@10240 (32x72 fp16, 4608)
//       invq@14848 (256), invk@15104 (256)  -> total 15360
// ---------------------------------------------------------------------------
#define QP  40
#define PPB 72
#define VTP 72
#define ATTN_SMEM_BYTES 15360

__global__ void __launch_bounds__(128) attn_kernel(const float* __restrict__ logit_scale)
{
    extern __shared__ char smb[];
    __half* qs  = (__half*)(smb);
    __half* ks  = (__half*)(smb + 5120);
    __half* pm  = (__half*)(smb);            // alias (after QK reads)
    __half* vt  = (__half*)(smb + 10240);
    float* invq = (float*)(smb + 14848);
    float* invk = (float*)(smb + 15104);

    const int bh = blockIdx.x;
    const int b  = bh >> 3;
    const int h  = bh & 7;
    const int tid  = threadIdx.x;
    const int lane = tid & 31;
    const int warp = tid >> 5;
    const int g  = lane >> 2, tg = lane & 3;
    const int m0 = warp * 16;
    const int r0 = m0 + g, r1 = r0 + 8;

    const size_t base = (size_t)bh * WIN * HD;
    const float ls = __expf(fminf(logit_scale[h], 4.6051701859880914f));

    // Phase 0: raw fp16 q/k copy + norms; v transpose
    {
        const int row = tid >> 1;
        const int d0  = (tid & 1) * 16;
        {
            uint32_t raw[8];
            const uint32_t* qp = (const uint32_t*)&g_qh[base + row * HD + d0];
            float s = 0.f;
            #pragma unroll
            for (int i = 0; i < 8; i++) {
                raw[i] = qp[i];
                float2 f = __half22float2(*(__half2*)&raw[i]);
                s += f.x * f.x + f.y * f.y;
            }
            s += __shfl_xor_sync(0xffffffffu, s, 1);
            if ((tid & 1) == 0) invq[row] = ls / fmaxf(sqrtf(s), 1e-12f);
            #pragma unroll
            for (int i = 0; i < 8; i++)
                *(uint32_t*)&qs[row * QP + d0 + 2 * i] = raw[i];
        }
        {
            uint32_t raw[8];
            const uint32_t* kp = (const uint32_t*)&g_kh[base + row * HD + d0];
            float s = 0.f;
            #pragma unroll
            for (int i = 0; i < 8; i++) {
                raw[i] = kp[i];
                float2 f = __half22float2(*(__half2*)&raw[i]);
                s += f.x * f.x + f.y * f.y;
            }
            s += __shfl_xor_sync(0xffffffffu, s, 1);
            if ((tid & 1) == 0) invk[row] = 1.0f / fmaxf(sqrtf(s), 1e-12f);
            #pragma unroll
            for (int i = 0; i < 8; i++)
                *(uint32_t*)&ks[row * QP + d0 + 2 * i] = raw[i];
        }
        #pragma unroll
        for (int i = 0; i < 4; i++) {
            const int idx = tid + 128 * i;
            const int n = idx >> 3, c = (idx & 7) * 4;
            const __half* vp = &g_vh[base + n * HD + c];
            __half2 v01 = *(const __half2*)(vp);
            __half2 v23 = *(const __half2*)(vp + 2);
            vt[(c + 0) * VTP + n] = __low2half(v01);
            vt[(c + 1) * VTP + n] = __high2half(v01);
            vt[(c + 2) * VTP + n] = __low2half(v23);
            vt[(c + 3) * VTP + n] = __high2half(v23);
        }
    }
    __syncthreads();

    // Prefetch bias+mask (fp16)
    float2 bm0[8], bm1[8];
    {
        const __half* bm = g_bmh + ((size_t)((b & 255) * 8 + h) << 12);
        #pragma unroll
        for (int an = 0; an < 8; an++) {
            const int c = an * 8 + 2 * tg;
            bm0[an] = __half22float2(*(const __half2*)&bm[r0 * 64 + c]);
            bm1[an] = __half22float2(*(const __half2*)&bm[r1 * 64 + c]);
        }
    }

    // QK^T: plain fp16 MMA (exact)
    float acc[8][4] = {};
    #pragma unroll
    for (int kst = 0; kst < 2; kst++) {
        const int kb = kst * 16;
        unsigned a0 = *(uint32_t*)&qs[(m0 + g)     * QP + kb + 2 * tg];
        unsigned a1 = *(uint32_t*)&qs[(m0 + g + 8) * QP + kb + 2 * tg];
        unsigned a2 = *(uint32_t*)&qs[(m0 + g)     * QP + kb + 2 * tg + 8];
        unsigned a3 = *(uint32_t*)&qs[(m0 + g + 8) * QP + kb + 2 * tg + 8];
        #pragma unroll
        for (int an = 0; an < 8; an++) {
            const int nr = an * 8;
            unsigned b0 = *(uint32_t*)&ks[(nr + g) * QP + kb + 2 * tg];
            unsigned b1 = *(uint32_t*)&ks[(nr + g) * QP + kb + 2 * tg + 8];
            mma_f16(acc[an], a0, a1, a2, a3, b0, b1);
        }
    }

    // Scale by norms + bias/mask
    const float iq0 = invq[r0], iq1 = invq[r1];
    #pragma unroll
    for (int an = 0; an < 8; an++) {
        const int c = an * 8 + 2 * tg;
        const float ik0 = invk[c], ik1 = invk[c + 1];
        acc[an][0] = acc[an][0] * iq0 * ik0 + bm0[an].x;
        acc[an][1] = acc[an][1] * iq0 * ik1 + bm0[an].y;
        acc[an][2] = acc[an][2] * iq1 * ik0 + bm1[an].x;
        acc[an][3] = acc[an][3] * iq1 * ik1 + bm1[an].y;
    }
    __syncthreads();   // all QK smem reads done before P writes alias q/k

    // Register softmax; write P fp16 (single term)
    {
        float m0v = -1e30f, m1v = -1e30f;
        #pragma unroll
        for (int an = 0; an < 8; an++) {
            m0v = fmaxf(m0v, fmaxf(acc[an][0], acc[an][1]));
            m1v = fmaxf(m1v, fmaxf(acc[an][2], acc[an][3]));
        }
        m0v = fmaxf(m0v, __shfl_xor_sync(0xffffffffu, m0v, 1));
        m0v = fmaxf(m0v, __shfl_xor_sync(0xffffffffu, m0v, 2));
        m1v = fmaxf(m1v, __shfl_xor_sync(0xffffffffu, m1v, 1));
        m1v = fmaxf(m1v, __shfl_xor_sync(0xffffffffu, m1v, 2));
        float s0 = 0.f, s1 = 0.f;
        #pragma unroll
        for (int an = 0; an < 8; an++) {
            acc[an][0] = __expf(acc[an][0] - m0v); s0 += acc[an][0];
            acc[an][1] = __expf(acc[an][1] - m0v); s0 += acc[an][1];
            acc[an][2] = __expf(acc[an][2] - m1v); s1 += acc[an][2];
            acc[an][3] = __expf(acc[an][3] - m1v); s1 += acc[an][3];
        }
        s0 += __shfl_xor_sync(0xffffffffu, s0, 1);
        s0 += __shfl_xor_sync(0xffffffffu, s0, 2);
        s1 += __shfl_xor_sync(0xffffffffu, s1, 1);
        s1 += __shfl_xor_sync(0xffffffffu, s1, 2);
        const float i0 = 1.0f / s0, i1 = 1.0f / s1;
        #pragma unroll
        for (int an = 0; an < 8; an++) {
            const int c = an * 8 + 2 * tg;
            *(uint32_t*)&pm[r0 * PPB + c] = pack_f16(acc[an][0] * i0, acc[an][1] * i0);
            *(uint32_t*)&pm[r1 * PPB + c] = pack_f16(acc[an][2] * i1, acc[an][3] * i1);
        }
    }
    __syncwarp();   // warp reads only its own 16 P-rows

    // P @ V: single fp16 pass
    float oacc[4][4] = {};
    #pragma unroll
    for (int kst = 0; kst < 4; kst++) {
        const int kb = kst * 16;
        unsigned a0 = *(uint32_t*)&pm[(m0 + g)     * PPB + kb + 2 * tg];
        unsigned a1 = *(uint32_t*)&pm[(m0 + g + 8) * PPB + kb + 2 * tg];
        unsigned a2 = *(uint32_t*)&pm[(m0 + g)     * PPB + kb + 2 * tg + 8];
        unsigned a3 = *(uint32_t*)&pm[(m0 + g + 8) * PPB + kb + 2 * tg + 8];
        #pragma unroll
        for (int dn = 0; dn < 4; dn++) {
            const int nn = dn * 8;
            unsigned b0 = *(uint32_t*)&vt[(nn + g) * VTP + kb + 2 * tg];
            unsigned b1 = *(uint32_t*)&vt[(nn + g) * VTP + kb + 2 * tg + 8];
            mma_f16(oacc[dn], a0, a1, a2, a3, b0, b1);
        }
    }

    __half* aop = g_aoh + (size_t)b * WIN * DIM + h * HD;
    #pragma unroll
    for (int dn = 0; dn < 4; dn++) {
        const int c = dn * 8 + 2 * tg;
        *(uint32_t*)&aop[(size_t)r0 * DIM + c] = pack_f16(oacc[dn][0], oacc[dn][1]);
        *(uint32_t*)&aop[(size_t)r1 * DIM + c] = pack_f16(oacc[dn][2], oacc[dn][3]);
    }
}

// ---------------------------------------------------------------------------
extern "C" void kernel_launch(void* const* d_in, const int* in_sizes, int n_in,
                              void* d_out, int out_size)
{
    const float* x        = (const float*)d_in[0];
    const float* mask     = (const float*)d_in[1];
    const float* qkv_w    = (const float*)d_in[2];
    const float* qkv_b    = (const float*)d_in[3];
    const float* proj_w   = (const float*)d_in[4];
    const float* proj_b   = (const float*)d_in[5];
    const float* lscale   = (const float*)d_in[6];
    const float* btable   = (const float*)d_in[7];
    const int*   rpi      = (const int*)d_in[8];
    float* out = (float*)d_out;

    cudaFuncSetAttribute(attn_kernel, cudaFuncAttributeMaxDynamicSharedMemorySize,
                         ATTN_SMEM_BYTES);

    __half *xh, *wqh, *wph, *aoh;
    cudaGetSymbolAddress((void**)&xh,  g_xh);
    cudaGetSymbolAddress((void**)&wqh, g_wqh);
    cudaGetSymbolAddress((void**)&wph, g_wph);
    cudaGetSymbolAddress((void**)&aoh, g_aoh);

    // 0) pre-passes
    conv_f16<<<(MROWS*DIM/4 + 255)/256, 256>>>(x, xh, MROWS*DIM/4);
    conv_f16<<<(QKV_N*DIM/4 + 255)/256, 256>>>(qkv_w, wqh, QKV_N*DIM/4);
    conv_f16<<<(DIM*DIM/4 + 255)/256, 256>>>(proj_w, wph, DIM*DIM/4);
    bm_pre<<<8192, 256>>>(btable, rpi, mask);

    // 1) QKV projection
    {
        dim3 grid(QKV_N / 128, MROWS / 128);
        mma_gemm<true><<<grid, 128>>>(xh, wqh, qkv_b, nullptr);
    }
    // 2) Attention per (window, head)
    {
        attn_kernel<<<NWIN * HEADS, 128, ATTN_SMEM_BYTES>>>(lscale);
    }
    // 3) Output projection
    {
        dim3 grid(DIM / 128, MROWS / 128);
        mma_gemm<false><<<grid, 128>>>(aoh, wph, proj_b, out);
    }
}